// round 1
// baseline (speedup 1.0000x reference)
#include <cuda_runtime.h>
#include <stdint.h>

#define DI __device__ __forceinline__

// Problem constants
constexpr int Bb = 8, Ls = 1024, Cc = 1024, Hh = 16, Dd = 64;
constexpr int BHn = Bb * Hh;      // 128
constexpr int MT  = Bb * Ls;      // 8192 tokens
constexpr int NQKV = 3 * Cc;      // 3072

// Scratch (device globals: allocation-free per harness rules)
__device__ float g_Q[BHn * Ls * Dd];          // 32 MB  (b,h,l,d)
__device__ float g_K[BHn * Ls * Dd];          // 32 MB
__device__ float g_V[BHn * Ls * Dd];          // 32 MB
__device__ float g_P[134217728];              // 512 MB: P[bh][j][i] = scaled logits (S^T)
__device__ float g_Mx[BHn * Ls];              // per-(bh,j) column max
__device__ float g_Zi[BHn * Ls];              // per-(bh,j) 1/sum(exp)
__device__ float g_Y[MT * Cc];                // 32 MB  (b,l,c) attention output

// ---------------------------------------------------------------------------
// tf32 helpers
// ---------------------------------------------------------------------------
DI float tfbits(float x) {
    unsigned u;
    asm("cvt.rna.tf32.f32 %0, %1;" : "=r"(u) : "f"(x));
    return __uint_as_float(u);
}

DI void mma8(float c[4], const unsigned a[4], const unsigned b[2]) {
    asm volatile(
        "mma.sync.aligned.m16n8k8.row.col.f32.tf32.tf32.f32 "
        "{%0,%1,%2,%3}, {%4,%5,%6,%7}, {%8,%9}, {%0,%1,%2,%3};"
        : "+f"(c[0]), "+f"(c[1]), "+f"(c[2]), "+f"(c[3])
        : "r"(a[0]), "r"(a[1]), "r"(a[2]), "r"(a[3]), "r"(b[0]), "r"(b[1]));
}

// ---------------------------------------------------------------------------
// K1 / K5: C = A(MxK row) * B(KxN row) + bias.  Tile 128x128, BK=32, 256 thr.
// EPI==1: scatter into g_Q/g_K/g_V per-head layout (QKV GEMM, N=3072)
// EPI==0: plain write to Cout (proj GEMM, N=1024), A source = g_Y
// ---------------------------------------------------------------------------
template <int NC, int EPI>
__global__ void __launch_bounds__(256, 1)
gemm_rr_kernel(const float* __restrict__ A, const float* __restrict__ Bm,
               const float* __restrict__ bias, float* __restrict__ Cout) {
    __shared__ float As[128][36];   // [m][k], pad 4 -> conflict-free frag reads
    __shared__ float Bs[32][132];   // [k][n], pad 4

    const float* Ap = (EPI == 0) ? (const float*)g_Y : A;

    const int t  = threadIdx.x;
    const int m0 = blockIdx.x * 128, n0 = blockIdx.y * 128;
    constexpr int K  = Cc;          // 1024
    constexpr int NK = K / 32;      // 32

    const int ar = t >> 3, ac = (t & 7) * 4;   // A loader: 4 rows (ar+32i), 16B chunk
    const int br = t >> 5, bc = (t & 31) * 4;  // B loader: 4 rows (br+8i)

    const int wid = t >> 5, lane = t & 31, lr = lane >> 2, lc = lane & 3;
    const int wm = (wid >> 2) * 64, wn = (wid & 3) * 32;

    float acc[4][4][4];
#pragma unroll
    for (int i = 0; i < 4; i++)
#pragma unroll
        for (int j = 0; j < 4; j++)
#pragma unroll
            for (int k = 0; k < 4; k++) acc[i][j][k] = 0.f;

    float4 ra[4], rb[4];

    // prologue load kt=0
#pragma unroll
    for (int i = 0; i < 4; i++)
        ra[i] = *(const float4*)(Ap + (size_t)(m0 + ar + i * 32) * K + ac);
#pragma unroll
    for (int i = 0; i < 4; i++)
        rb[i] = *(const float4*)(Bm + (size_t)(br + i * 8) * NC + n0 + bc);

#pragma unroll 1
    for (int kt = 0; kt < NK; kt++) {
        // store staged regs -> smem (tf32-rounded)
#pragma unroll
        for (int i = 0; i < 4; i++) {
            float4 v = ra[i];
            float4 w = make_float4(tfbits(v.x), tfbits(v.y), tfbits(v.z), tfbits(v.w));
            *(float4*)&As[ar + i * 32][ac] = w;
        }
#pragma unroll
        for (int i = 0; i < 4; i++) {
            float4 v = rb[i];
            float4 w = make_float4(tfbits(v.x), tfbits(v.y), tfbits(v.z), tfbits(v.w));
            *(float4*)&Bs[br + i * 8][bc] = w;
        }
        __syncthreads();

        if (kt + 1 < NK) {
            int kk = (kt + 1) * 32;
#pragma unroll
            for (int i = 0; i < 4; i++)
                ra[i] = *(const float4*)(Ap + (size_t)(m0 + ar + i * 32) * K + kk + ac);
#pragma unroll
            for (int i = 0; i < 4; i++)
                rb[i] = *(const float4*)(Bm + (size_t)(kk + br + i * 8) * NC + n0 + bc);
        }

#pragma unroll
        for (int ks = 0; ks < 4; ks++) {
            unsigned af[4][4], bf[4][2];
            const int k = ks * 8 + lc;
#pragma unroll
            for (int im = 0; im < 4; im++) {
                int r = wm + im * 16 + lr;
                af[im][0] = __float_as_uint(As[r][k]);
                af[im][1] = __float_as_uint(As[r + 8][k]);
                af[im][2] = __float_as_uint(As[r][k + 4]);
                af[im][3] = __float_as_uint(As[r + 8][k + 4]);
            }
#pragma unroll
            for (int in_ = 0; in_ < 4; in_++) {
                int n = wn + in_ * 8 + lr;
                bf[in_][0] = __float_as_uint(Bs[k][n]);
                bf[in_][1] = __float_as_uint(Bs[k + 4][n]);
            }
#pragma unroll
            for (int im = 0; im < 4; im++)
#pragma unroll
                for (int in_ = 0; in_ < 4; in_++) mma8(acc[im][in_], af[im], bf[in_]);
        }
        __syncthreads();
    }

    // epilogue
#pragma unroll
    for (int im = 0; im < 4; im++) {
#pragma unroll
        for (int in_ = 0; in_ < 4; in_++) {
            int r0 = m0 + wm + im * 16 + lr;
            int c0 = n0 + wn + in_ * 8 + lc * 2;
            float bz0 = bias[c0], bz1 = bias[c0 + 1];
#pragma unroll
            for (int h2 = 0; h2 < 2; h2++) {
                int r = r0 + h2 * 8;
                float v0 = acc[im][in_][h2 * 2 + 0] + bz0;
                float v1 = acc[im][in_][h2 * 2 + 1] + bz1;
                if (EPI == 0) {
                    float2 o = make_float2(v0, v1);
                    *(float2*)&Cout[(size_t)r * NC + c0] = o;
                } else {
                    int sec = c0 >> 10, w = c0 & 1023;
                    int hh = w >> 6, dd = w & 63;
                    int bi = r >> 10, li = r & 1023;
                    float* dst = (sec == 0) ? g_Q : (sec == 1) ? g_K : g_V;
                    float2 o = make_float2(v0, v1);
                    *(float2*)&dst[(((size_t)(bi * Hh + hh)) * Ls + li) * Dd + dd] = o;
                }
            }
        }
    }
}

// ---------------------------------------------------------------------------
// K2: logits  P[bh][j][i] = 0.125 * dot(K[bh,j,:], Q[bh,i,:]),  i>=j valid,
//      masked entries (i<j, diagonal tile only) stored as -1e30.
// Only lower-triangular tiles (it >= jt) launched usefully.
// ---------------------------------------------------------------------------
__global__ void __launch_bounds__(256, 1) logits_kernel() {
    const int it = blockIdx.x, jt = blockIdx.y, bh = blockIdx.z;
    if (it < jt) return;

    __shared__ float Ks[128][36];  // rows j, cols dd
    __shared__ float Qs[128][36];  // rows i, cols dd

    const float* Kp = g_K + (size_t)bh * Ls * Dd + (size_t)jt * 128 * Dd;
    const float* Qp = g_Q + (size_t)bh * Ls * Dd + (size_t)it * 128 * Dd;

    const int t = threadIdx.x;
    const int r = t >> 3, c = (t & 7) * 4;
    const int wid = t >> 5, lane = t & 31, lr = lane >> 2, lc = lane & 3;
    const int wm = (wid >> 2) * 64, wn = (wid & 3) * 32;

    float acc[4][4][4];
#pragma unroll
    for (int i = 0; i < 4; i++)
#pragma unroll
        for (int j = 0; j < 4; j++)
#pragma unroll
            for (int k = 0; k < 4; k++) acc[i][j][k] = 0.f;

#pragma unroll
    for (int kt = 0; kt < 2; kt++) {
        int kk = kt * 32;
#pragma unroll
        for (int i = 0; i < 4; i++) {
            float4 v = *(const float4*)(Kp + (size_t)(r + i * 32) * Dd + kk + c);
            *(float4*)&Ks[r + i * 32][c] =
                make_float4(tfbits(v.x), tfbits(v.y), tfbits(v.z), tfbits(v.w));
            float4 q = *(const float4*)(Qp + (size_t)(r + i * 32) * Dd + kk + c);
            *(float4*)&Qs[r + i * 32][c] =
                make_float4(tfbits(q.x), tfbits(q.y), tfbits(q.z), tfbits(q.w));
        }
        __syncthreads();

#pragma unroll
        for (int ks = 0; ks < 4; ks++) {
            unsigned af[4][4], bf[4][2];
            const int k = ks * 8 + lc;
#pragma unroll
            for (int im = 0; im < 4; im++) {
                int rr = wm + im * 16 + lr;
                af[im][0] = __float_as_uint(Ks[rr][k]);
                af[im][1] = __float_as_uint(Ks[rr + 8][k]);
                af[im][2] = __float_as_uint(Ks[rr][k + 4]);
                af[im][3] = __float_as_uint(Ks[rr + 8][k + 4]);
            }
#pragma unroll
            for (int in_ = 0; in_ < 4; in_++) {
                int n = wn + in_ * 8 + lr;
                bf[in_][0] = __float_as_uint(Qs[n][k]);
                bf[in_][1] = __float_as_uint(Qs[n][k + 4]);
            }
#pragma unroll
            for (int im = 0; im < 4; im++)
#pragma unroll
                for (int in_ = 0; in_ < 4; in_++) mma8(acc[im][in_], af[im], bf[in_]);
        }
        __syncthreads();
    }

    const size_t base = (size_t)bh * Ls * Ls;
#pragma unroll
    for (int im = 0; im < 4; im++) {
#pragma unroll
        for (int in_ = 0; in_ < 4; in_++) {
            int r0 = jt * 128 + wm + im * 16 + lr;
            int c0 = it * 128 + wn + in_ * 8 + lc * 2;
#pragma unroll
            for (int h2 = 0; h2 < 2; h2++) {
                int rr = r0 + h2 * 8;
                float v0 = (c0 >= rr) ? acc[im][in_][h2 * 2 + 0] * 0.125f : -1e30f;
                float v1 = (c0 + 1 >= rr) ? acc[im][in_][h2 * 2 + 1] * 0.125f : -1e30f;
                float2 o = make_float2(v0, v1);
                *(float2*)&g_P[base + (size_t)rr * Ls + c0] = o;
            }
        }
    }
}

// ---------------------------------------------------------------------------
// K3: per-row (key j) online softmax stats over i in [tile_start(j), L).
// One warp per row; 8 rows per CTA.
// ---------------------------------------------------------------------------
DI void onl(float& m, float& z, float x) {
    if (x > m) {
        z = z * __expf(m - x) + 1.f;
        m = x;
    } else {
        z += __expf(x - m);
    }
}

__global__ void __launch_bounds__(256) stats_kernel() {
    const int row = blockIdx.x * 8 + (threadIdx.x >> 5);
    const int lane = threadIdx.x & 31;
    const int bh = row >> 10, j = row & 1023;
    const float* p = g_P + (size_t)bh * Ls * Ls + (size_t)j * Ls;
    const int istart = j & ~127;

    float m = -3.0e38f, z = 0.f;
    for (int i = istart + lane * 4; i < Ls; i += 128) {
        float4 v = *(const float4*)(p + i);
        onl(m, z, v.x); onl(m, z, v.y); onl(m, z, v.z); onl(m, z, v.w);
    }
#pragma unroll
    for (int off = 16; off; off >>= 1) {
        float mo = __shfl_xor_sync(0xFFFFFFFFu, m, off);
        float zo = __shfl_xor_sync(0xFFFFFFFFu, z, off);
        if (mo > m) {
            z = z * __expf(m - mo) + zo;
            m = mo;
        } else {
            z = z + zo * __expf(mo - m);
        }
    }
    if (lane == 0) {
        g_Mx[row] = m;
        g_Zi[row] = 1.f / z;
    }
}

// ---------------------------------------------------------------------------
// K4: y[i,d] = sum_j softmax_w(P[j,i]) * V[j,d], per (bh, i-tile of 128).
// A tile = transformed P^T (exp applied on load), B tile = V.
// ---------------------------------------------------------------------------
__global__ void __launch_bounds__(256, 1) pv_kernel() {
    const int it = blockIdx.x, bh = blockIdx.y;

    __shared__ float As4[128][36];  // [i][j]
    __shared__ float Bs4[32][68];   // [j][d]

    const int t = threadIdx.x;
    const int NK = (it + 1) * 4;
    const size_t Pbase = (size_t)bh * Ls * Ls;
    const float* Vp = g_V + (size_t)bh * Ls * Dd;
    const float* Mp = g_Mx + bh * Ls;
    const float* Zp = g_Zi + bh * Ls;
    const int m0 = it * 128;

    const int jr = t >> 3, icb = (t & 7);     // A loader: fixed row j=jr
    const int vr = t >> 4, vc = (t & 15) * 4; // B loader
    const int wid = t >> 5, lane = t & 31, lr = lane >> 2, lc = lane & 3;
    const int wm = (wid >> 1) * 32, wn = (wid & 1) * 32;

    float acc[2][4][4];
#pragma unroll
    for (int i = 0; i < 2; i++)
#pragma unroll
        for (int j = 0; j < 4; j++)
#pragma unroll
            for (int k = 0; k < 4; k++) acc[i][j][k] = 0.f;

#pragma unroll 1
    for (int kt = 0; kt < NK; kt++) {
        const int kk = kt * 32;
        const float mj = Mp[kk + jr];
        const float zj = Zp[kk + jr];
        const float* prow = g_P + Pbase + (size_t)(kk + jr) * Ls + m0;
#pragma unroll
        for (int s = 0; s < 4; s++) {
            int i0 = icb * 4 + s * 32;
            float4 v = *(const float4*)(prow + i0);
            As4[i0 + 0][jr] = tfbits(__expf(v.x - mj) * zj);
            As4[i0 + 1][jr] = tfbits(__expf(v.y - mj) * zj);
            As4[i0 + 2][jr] = tfbits(__expf(v.z - mj) * zj);
            As4[i0 + 3][jr] = tfbits(__expf(v.w - mj) * zj);
        }
#pragma unroll
        for (int s = 0; s < 2; s++) {
            float4 v = *(const float4*)(Vp + (size_t)(kk + vr + s * 16) * Dd + vc);
            *(float4*)&Bs4[vr + s * 16][vc] =
                make_float4(tfbits(v.x), tfbits(v.y), tfbits(v.z), tfbits(v.w));
        }
        __syncthreads();

#pragma unroll
        for (int ks = 0; ks < 4; ks++) {
            unsigned af[2][4], bf[4][2];
            const int k = ks * 8 + lc;
#pragma unroll
            for (int im = 0; im < 2; im++) {
                int rr = wm + im * 16 + lr;
                af[im][0] = __float_as_uint(As4[rr][k]);
                af[im][1] = __float_as_uint(As4[rr + 8][k]);
                af[im][2] = __float_as_uint(As4[rr][k + 4]);
                af[im][3] = __float_as_uint(As4[rr + 8][k + 4]);
            }
#pragma unroll
            for (int in_ = 0; in_ < 4; in_++) {
                int n = wn + in_ * 8 + lr;
                bf[in_][0] = __float_as_uint(Bs4[k][n]);
                bf[in_][1] = __float_as_uint(Bs4[k + 4][n]);
            }
#pragma unroll
            for (int im = 0; im < 2; im++)
#pragma unroll
                for (int in_ = 0; in_ < 4; in_++) mma8(acc[im][in_], af[im], bf[in_]);
        }
        __syncthreads();
    }

    const int b = bh >> 4, h = bh & 15;
#pragma unroll
    for (int im = 0; im < 2; im++) {
#pragma unroll
        for (int in_ = 0; in_ < 4; in_++) {
            int r0 = m0 + wm + im * 16 + lr;
            int c0 = wn + in_ * 8 + lc * 2;
#pragma unroll
            for (int h2 = 0; h2 < 2; h2++) {
                int rr = r0 + h2 * 8;
                float2 o = make_float2(acc[im][in_][h2 * 2 + 0],
                                       acc[im][in_][h2 * 2 + 1]);
                *(float2*)&g_Y[((size_t)(b * Ls + rr)) * Cc + h * Dd + c0] = o;
            }
        }
    }
}

// ---------------------------------------------------------------------------
// Launch
// ---------------------------------------------------------------------------
extern "C" void kernel_launch(void* const* d_in, const int* in_sizes, int n_in,
                              void* d_out, int out_size) {
    const float* x     = (const float*)d_in[0];
    const float* Wqkv  = (const float*)d_in[1];
    const float* bqkv  = (const float*)d_in[2];
    const float* Wproj = (const float*)d_in[3];
    const float* bproj = (const float*)d_in[4];
    float* out = (float*)d_out;

    // K1: QKV projection, scatter into per-head Q/K/V
    gemm_rr_kernel<NQKV, 1><<<dim3(MT / 128, NQKV / 128), 256>>>(x, Wqkv, bqkv, nullptr);
    // K2: masked logits S^T into g_P (lower-triangular tiles only)
    logits_kernel<<<dim3(8, 8, BHn), 256>>>();
    // K3: per-key-column softmax stats
    stats_kernel<<<(BHn * Ls) / 8, 256>>>();
    // K4: y = softmax_w(P)^T @ V
    pv_kernel<<<dim3(8, BHn), 256>>>();
    // K5: output projection
    gemm_rr_kernel<Cc, 0><<<dim3(MT / 128, Cc / 128), 256>>>(nullptr, Wproj, bproj, out);
}

// round 3
// speedup vs baseline: 1.1197x; 1.1197x over previous
#include <cuda_runtime.h>
#include <stdint.h>

#define DI __device__ __forceinline__

// Problem constants
constexpr int Bb = 8, Ls = 1024, Cc = 1024, Hh = 16, Dd = 64;
constexpr int BHn = Bb * Hh;      // 128
constexpr int MT  = Bb * Ls;      // 8192 tokens
constexpr int NQKV = 3 * Cc;      // 3072

// Scratch (device globals: allocation-free per harness rules)
__device__ float g_Q[BHn * Ls * Dd];          // 32 MB  (b,h,l,d)
__device__ float g_K[BHn * Ls * Dd];          // 32 MB
__device__ float g_V[BHn * Ls * Dd];          // 32 MB
__device__ float g_Mx[BHn * Ls];              // per-(bh,j) column max
__device__ float g_Zi[BHn * Ls];              // per-(bh,j) 1/sum(exp)
__device__ float g_Y[MT * Cc];                // 32 MB  (b,l,c) attention output

// ---------------------------------------------------------------------------
// tf32 helpers
// ---------------------------------------------------------------------------
DI float tfbits(float x) {
    unsigned u;
    asm("cvt.rna.tf32.f32 %0, %1;" : "=r"(u) : "f"(x));
    return __uint_as_float(u);
}
DI float4 tf4(float4 v) {
    return make_float4(tfbits(v.x), tfbits(v.y), tfbits(v.z), tfbits(v.w));
}

DI void mma8(float c[4], const unsigned a[4], const unsigned b[2]) {
    asm volatile(
        "mma.sync.aligned.m16n8k8.row.col.f32.tf32.tf32.f32 "
        "{%0,%1,%2,%3}, {%4,%5,%6,%7}, {%8,%9}, {%0,%1,%2,%3};"
        : "+f"(c[0]), "+f"(c[1]), "+f"(c[2]), "+f"(c[3])
        : "r"(a[0]), "r"(a[1]), "r"(a[2]), "r"(a[3]), "r"(b[0]), "r"(b[1]));
}

DI void onl(float& m, float& z, float x) {
    if (x > m) {
        z = z * __expf(m - x) + 1.f;
        m = x;
    } else {
        z += __expf(x - m);
    }
}

// ---------------------------------------------------------------------------
// K1 / K5: C = A(MxK row) * B(KxN row) + bias.  Tile 128x128, BK=32, 256 thr.
// EPI==1: scatter into g_Q/g_K/g_V per-head layout (QKV GEMM, N=3072)
// EPI==0: plain write to Cout (proj GEMM, N=1024), A source = g_Y
// ---------------------------------------------------------------------------
template <int NC, int EPI>
__global__ void __launch_bounds__(256, 2)
gemm_rr_kernel(const float* __restrict__ A, const float* __restrict__ Bm,
               const float* __restrict__ bias, float* __restrict__ Cout) {
    __shared__ float As[128][36];   // [m][k]
    __shared__ float Bs[32][132];   // [k][n]

    const float* Ap = (EPI == 0) ? (const float*)g_Y : A;

    const int t  = threadIdx.x;
    const int m0 = blockIdx.x * 128, n0 = blockIdx.y * 128;
    constexpr int K  = Cc;          // 1024
    constexpr int NK = K / 32;      // 32

    const int ar = t >> 3, ac = (t & 7) * 4;
    const int br = t >> 5, bc = (t & 31) * 4;

    const int wid = t >> 5, lane = t & 31, lr = lane >> 2, lc = lane & 3;
    const int wm = (wid >> 2) * 64, wn = (wid & 3) * 32;

    float acc[4][4][4];
#pragma unroll
    for (int i = 0; i < 4; i++)
#pragma unroll
        for (int j = 0; j < 4; j++)
#pragma unroll
            for (int k = 0; k < 4; k++) acc[i][j][k] = 0.f;

    float4 ra[4], rb[4];

#pragma unroll
    for (int i = 0; i < 4; i++)
        ra[i] = *(const float4*)(Ap + (size_t)(m0 + ar + i * 32) * K + ac);
#pragma unroll
    for (int i = 0; i < 4; i++)
        rb[i] = *(const float4*)(Bm + (size_t)(br + i * 8) * NC + n0 + bc);

#pragma unroll 1
    for (int kt = 0; kt < NK; kt++) {
#pragma unroll
        for (int i = 0; i < 4; i++) *(float4*)&As[ar + i * 32][ac] = tf4(ra[i]);
#pragma unroll
        for (int i = 0; i < 4; i++) *(float4*)&Bs[br + i * 8][bc] = tf4(rb[i]);
        __syncthreads();

        if (kt + 1 < NK) {
            int kk = (kt + 1) * 32;
#pragma unroll
            for (int i = 0; i < 4; i++)
                ra[i] = *(const float4*)(Ap + (size_t)(m0 + ar + i * 32) * K + kk + ac);
#pragma unroll
            for (int i = 0; i < 4; i++)
                rb[i] = *(const float4*)(Bm + (size_t)(kk + br + i * 8) * NC + n0 + bc);
        }

#pragma unroll
        for (int ks = 0; ks < 4; ks++) {
            unsigned af[4][4], bf[4][2];
            const int k = ks * 8 + lc;
#pragma unroll
            for (int im = 0; im < 4; im++) {
                int r = wm + im * 16 + lr;
                af[im][0] = __float_as_uint(As[r][k]);
                af[im][1] = __float_as_uint(As[r + 8][k]);
                af[im][2] = __float_as_uint(As[r][k + 4]);
                af[im][3] = __float_as_uint(As[r + 8][k + 4]);
            }
#pragma unroll
            for (int in_ = 0; in_ < 4; in_++) {
                int n = wn + in_ * 8 + lr;
                bf[in_][0] = __float_as_uint(Bs[k][n]);
                bf[in_][1] = __float_as_uint(Bs[k + 4][n]);
            }
#pragma unroll
            for (int im = 0; im < 4; im++)
#pragma unroll
                for (int in_ = 0; in_ < 4; in_++) mma8(acc[im][in_], af[im], bf[in_]);
        }
        __syncthreads();
    }

#pragma unroll
    for (int im = 0; im < 4; im++) {
#pragma unroll
        for (int in_ = 0; in_ < 4; in_++) {
            int r0 = m0 + wm + im * 16 + lr;
            int c0 = n0 + wn + in_ * 8 + lc * 2;
            float bz0 = bias[c0], bz1 = bias[c0 + 1];
#pragma unroll
            for (int h2 = 0; h2 < 2; h2++) {
                int r = r0 + h2 * 8;
                float v0 = acc[im][in_][h2 * 2 + 0] + bz0;
                float v1 = acc[im][in_][h2 * 2 + 1] + bz1;
                if (EPI == 0) {
                    *(float2*)&Cout[(size_t)r * NC + c0] = make_float2(v0, v1);
                } else {
                    int sec = c0 >> 10, w = c0 & 1023;
                    int hh = w >> 6, dd = w & 63;
                    int bi = r >> 10, li = r & 1023;
                    float* dst = (sec == 0) ? g_Q : (sec == 1) ? g_K : g_V;
                    *(float2*)&dst[(((size_t)(bi * Hh + hh)) * Ls + li) * Dd + dd] =
                        make_float2(v0, v1);
                }
            }
        }
    }
}

// ---------------------------------------------------------------------------
// Pass 1: per-key-column softmax stats, with S recomputed on tensor cores.
// CTA = (jt, bh). K-tile fragments live in registers; Q-tiles streamed.
// smem: Ksm[128][68] + Qsm[128][68]  (stride 68 -> conflict-free frag loads)
// ---------------------------------------------------------------------------
constexpr int P1_SMEM = (128 * 68 + 128 * 68) * 4;   // 69632 B

__global__ void __launch_bounds__(256, 2) stats_kernel2() {
    extern __shared__ float sm1[];
    float* Ksm = sm1;              // [128][68]
    float* Qsm = sm1 + 128 * 68;   // [128][68]

    const int jt = blockIdx.x, bh = blockIdx.y;   // jt=0 (heaviest) first
    const int t = threadIdx.x;
    const int lane = t & 31, wid = t >> 5;
    const int lr = lane >> 2, lc = lane & 3;
    const int wm = wid * 16;
    const int lrow = t >> 4, lcol = (t & 15) * 4;

    const float* Kp = g_K + ((size_t)bh * Ls + jt * 128) * Dd;
    const float* Qp = g_Q + (size_t)bh * Ls * Dd;

    // load K tile (tf32-rounded)
#pragma unroll
    for (int i = 0; i < 8; i++) {
        int r = i * 16 + lrow;
        float4 v = *(const float4*)(Kp + (size_t)r * Dd + lcol);
        *(float4*)&Ksm[r * 68 + lcol] = tf4(v);
    }
    // prefetch first Q tile
    float4 rq[8];
#pragma unroll
    for (int i = 0; i < 8; i++) {
        int r = i * 16 + lrow;
        rq[i] = *(const float4*)(Qp + (size_t)(jt * 128 + r) * Dd + lcol);
    }
    __syncthreads();

    // K fragments (A operand), fixed for whole kernel
    unsigned af[8][4];
#pragma unroll
    for (int ks = 0; ks < 8; ks++) {
        int k = ks * 8 + lc;
        af[ks][0] = __float_as_uint(Ksm[(wm + lr) * 68 + k]);
        af[ks][1] = __float_as_uint(Ksm[(wm + lr + 8) * 68 + k]);
        af[ks][2] = __float_as_uint(Ksm[(wm + lr) * 68 + k + 4]);
        af[ks][3] = __float_as_uint(Ksm[(wm + lr + 8) * 68 + k + 4]);
    }

    float m0 = -3e38f, z0 = 0.f, m1 = -3e38f, z1 = 0.f;
    const int j0 = jt * 128 + wm + lr;
    const int j1 = j0 + 8;

    for (int it = jt; it < 8; it++) {
#pragma unroll
        for (int i = 0; i < 8; i++) {
            int r = i * 16 + lrow;
            *(float4*)&Qsm[r * 68 + lcol] = tf4(rq[i]);
        }
        __syncthreads();
        if (it + 1 < 8) {
#pragma unroll
            for (int i = 0; i < 8; i++) {
                int r = i * 16 + lrow;
                rq[i] = *(const float4*)(Qp + (size_t)((it + 1) * 128 + r) * Dd + lcol);
            }
        }
        const bool diag = (it == jt);
#pragma unroll
        for (int nt = 0; nt < 16; nt++) {
            float acc[4] = {0.f, 0.f, 0.f, 0.f};
#pragma unroll
            for (int ks = 0; ks < 8; ks++) {
                unsigned bf[2];
                int k = ks * 8 + lc;
                bf[0] = __float_as_uint(Qsm[(nt * 8 + lr) * 68 + k]);
                bf[1] = __float_as_uint(Qsm[(nt * 8 + lr) * 68 + k + 4]);
                mma8(acc, af[ks], bf);
            }
            int i0 = it * 128 + nt * 8 + lc * 2;
            if (!diag || i0 >= j0)     onl(m0, z0, acc[0] * 0.125f);
            if (!diag || i0 + 1 >= j0) onl(m0, z0, acc[1] * 0.125f);
            if (!diag || i0 >= j1)     onl(m1, z1, acc[2] * 0.125f);
            if (!diag || i0 + 1 >= j1) onl(m1, z1, acc[3] * 0.125f);
        }
        __syncthreads();
    }

    // reduce across the 4 lanes sharing a row (lane = lr*4 + lc)
#pragma unroll
    for (int off = 1; off <= 2; off <<= 1) {
        float mo = __shfl_xor_sync(0xFFFFFFFFu, m0, off);
        float zo = __shfl_xor_sync(0xFFFFFFFFu, z0, off);
        if (mo > m0) { z0 = z0 * __expf(m0 - mo) + zo; m0 = mo; }
        else         { z0 += zo * __expf(mo - m0); }
        mo = __shfl_xor_sync(0xFFFFFFFFu, m1, off);
        zo = __shfl_xor_sync(0xFFFFFFFFu, z1, off);
        if (mo > m1) { z1 = z1 * __expf(m1 - mo) + zo; m1 = mo; }
        else         { z1 += zo * __expf(mo - m1); }
    }
    if (lc == 0) {
        g_Mx[bh * Ls + j0] = m0;
        g_Zi[bh * Ls + j0] = 1.f / z0;
        g_Mx[bh * Ls + j1] = m1;
        g_Zi[bh * Ls + j1] = 1.f / z1;
    }
}

// ---------------------------------------------------------------------------
// Pass 2: y[i,d] = sum_{j<=i} exp(s_ij - m_j) * Zi_j * v[j,d].
// CTA = (it, bh). Q fragments in registers; per j-tile:
//   GEMM1 (Q x K^T) -> w -> Ws (warp-private rows) -> GEMM2 (Ws x V).
// smem: Ws[128][132] | Ksm[128][68] | Vsm[128][72] | ms[128] | zs[128]
// ---------------------------------------------------------------------------
constexpr int P2_WS = 0;
constexpr int P2_KS = 128 * 132;                 // 16896
constexpr int P2_VS = P2_KS + 128 * 68;          // 25600
constexpr int P2_MS = P2_VS + 128 * 72;          // 34816
constexpr int P2_ZS = P2_MS + 128;               // 34944
constexpr int P2_SMEM = (P2_ZS + 128) * 4;       // 140288 B

__global__ void __launch_bounds__(256, 1) attn_kernel2() {
    extern __shared__ float sm2[];
    float* Ws  = sm2 + P2_WS;
    float* Ksm = sm2 + P2_KS;
    float* Vsm = sm2 + P2_VS;
    float* msm = sm2 + P2_MS;
    float* zsm = sm2 + P2_ZS;

    const int it = 7 - blockIdx.x;               // heavy tiles first
    const int bh = blockIdx.y;
    const int b = bh >> 4, h = bh & 15;
    const int t = threadIdx.x;
    const int lane = t & 31, wid = t >> 5;
    const int lr = lane >> 2, lc = lane & 3;
    const int wm = wid * 16;
    const int lrow = t >> 4, lcol = (t & 15) * 4;

    const float* Qp = g_Q + ((size_t)bh * Ls + it * 128) * Dd;
    const float* Kp = g_K + (size_t)bh * Ls * Dd;
    const float* Vp = g_V + (size_t)bh * Ls * Dd;

    // stage Q into Ws area (stride 68), read fragments, then Ws is reused
#pragma unroll
    for (int i = 0; i < 8; i++) {
        int r = i * 16 + lrow;
        float4 v = *(const float4*)(Qp + (size_t)r * Dd + lcol);
        *(float4*)&Ws[r * 68 + lcol] = tf4(v);
    }
    __syncthreads();
    unsigned qf[8][4];
#pragma unroll
    for (int ks = 0; ks < 8; ks++) {
        int k = ks * 8 + lc;
        qf[ks][0] = __float_as_uint(Ws[(wm + lr) * 68 + k]);
        qf[ks][1] = __float_as_uint(Ws[(wm + lr + 8) * 68 + k]);
        qf[ks][2] = __float_as_uint(Ws[(wm + lr) * 68 + k + 4]);
        qf[ks][3] = __float_as_uint(Ws[(wm + lr + 8) * 68 + k + 4]);
    }

    float yacc[8][4];
#pragma unroll
    for (int i = 0; i < 8; i++)
#pragma unroll
        for (int q = 0; q < 4; q++) yacc[i][q] = 0.f;

    // prefetch tile 0
    float4 rk[8], rv[8];
    float rstat;
#pragma unroll
    for (int i = 0; i < 8; i++) {
        int r = i * 16 + lrow;
        rk[i] = *(const float4*)(Kp + (size_t)r * Dd + lcol);
        rv[i] = *(const float4*)(Vp + (size_t)r * Dd + lcol);
    }
    rstat = (t < 128) ? g_Mx[bh * Ls + t] : g_Zi[bh * Ls + (t - 128)];

    const int i0r = it * 128 + wm + lr;
    const int i1r = i0r + 8;

#pragma unroll 1
    for (int kt = 0; kt <= it; kt++) {
        __syncthreads();   // prior GEMM2 reads / qf reads complete
#pragma unroll
        for (int i = 0; i < 8; i++) {
            int r = i * 16 + lrow;
            *(float4*)&Ksm[r * 68 + lcol] = tf4(rk[i]);
            *(float4*)&Vsm[r * 72 + lcol] = tf4(rv[i]);
        }
        if (t < 128) msm[t] = rstat; else zsm[t - 128] = rstat;
        __syncthreads();

        if (kt < it) {
            int roff = (kt + 1) * 128;
#pragma unroll
            for (int i = 0; i < 8; i++) {
                int r = roff + i * 16 + lrow;
                rk[i] = *(const float4*)(Kp + (size_t)r * Dd + lcol);
                rv[i] = *(const float4*)(Vp + (size_t)r * Dd + lcol);
            }
            rstat = (t < 128) ? g_Mx[bh * Ls + roff + t]
                              : g_Zi[bh * Ls + roff + (t - 128)];
        }

        const bool diag = (kt == it);
        // GEMM1: S tile + softmax weights into warp-private Ws rows
#pragma unroll
        for (int nt = 0; nt < 16; nt++) {
            float acc[4] = {0.f, 0.f, 0.f, 0.f};
#pragma unroll
            for (int ks = 0; ks < 8; ks++) {
                unsigned bf[2];
                int k = ks * 8 + lc;
                bf[0] = __float_as_uint(Ksm[(nt * 8 + lr) * 68 + k]);
                bf[1] = __float_as_uint(Ksm[(nt * 8 + lr) * 68 + k + 4]);
                mma8(acc, qf[ks], bf);
            }
            int jl = nt * 8 + lc * 2;
            float mj0 = msm[jl], zj0 = zsm[jl];
            float mj1 = msm[jl + 1], zj1 = zsm[jl + 1];
            float w00 = __expf(acc[0] * 0.125f - mj0) * zj0;
            float w01 = __expf(acc[1] * 0.125f - mj1) * zj1;
            float w10 = __expf(acc[2] * 0.125f - mj0) * zj0;
            float w11 = __expf(acc[3] * 0.125f - mj1) * zj1;
            if (diag) {
                int jg = kt * 128 + jl;
                if (i0r < jg)     w00 = 0.f;
                if (i0r < jg + 1) w01 = 0.f;
                if (i1r < jg)     w10 = 0.f;
                if (i1r < jg + 1) w11 = 0.f;
            }
            *(float2*)&Ws[(wm + lr) * 132 + jl] = make_float2(tfbits(w00), tfbits(w01));
            *(float2*)&Ws[(wm + lr + 8) * 132 + jl] = make_float2(tfbits(w10), tfbits(w11));
        }
        __syncwarp();   // warp-private Ws rows: warp-level ordering suffices

        // GEMM2: Y += Ws x V
#pragma unroll
        for (int ks = 0; ks < 16; ks++) {
            int k = ks * 8 + lc;
            unsigned a2[4];
            a2[0] = __float_as_uint(Ws[(wm + lr) * 132 + k]);
            a2[1] = __float_as_uint(Ws[(wm + lr + 8) * 132 + k]);
            a2[2] = __float_as_uint(Ws[(wm + lr) * 132 + k + 4]);
            a2[3] = __float_as_uint(Ws[(wm + lr + 8) * 132 + k + 4]);
#pragma unroll
            for (int dt = 0; dt < 8; dt++) {
                unsigned b2[2];
                b2[0] = __float_as_uint(Vsm[k * 72 + dt * 8 + lr]);
                b2[1] = __float_as_uint(Vsm[(k + 4) * 72 + dt * 8 + lr]);
                mma8(yacc[dt], a2, b2);
            }
        }
    }

    // epilogue -> g_Y (b, l, c)
#pragma unroll
    for (int dt = 0; dt < 8; dt++) {
        int d0 = dt * 8 + lc * 2;
        *(float2*)&g_Y[((size_t)(b * Ls + i0r)) * Cc + h * Dd + d0] =
            make_float2(yacc[dt][0], yacc[dt][1]);
        *(float2*)&g_Y[((size_t)(b * Ls + i1r)) * Cc + h * Dd + d0] =
            make_float2(yacc[dt][2], yacc[dt][3]);
    }
}

// ---------------------------------------------------------------------------
// Launch
// ---------------------------------------------------------------------------
extern "C" void kernel_launch(void* const* d_in, const int* in_sizes, int n_in,
                              void* d_out, int out_size) {
    const float* x     = (const float*)d_in[0];
    const float* Wqkv  = (const float*)d_in[1];
    const float* bqkv  = (const float*)d_in[2];
    const float* Wproj = (const float*)d_in[3];
    const float* bproj = (const float*)d_in[4];
    float* out = (float*)d_out;

    // idempotent; legal during graph capture (not a stream op)
    (void)cudaFuncSetAttribute(stats_kernel2,
                               cudaFuncAttributeMaxDynamicSharedMemorySize, P1_SMEM);
    (void)cudaFuncSetAttribute(attn_kernel2,
                               cudaFuncAttributeMaxDynamicSharedMemorySize, P2_SMEM);

    // K1: QKV projection, scatter into per-head Q/K/V
    gemm_rr_kernel<NQKV, 1><<<dim3(MT / 128, NQKV / 128), 256>>>(x, Wqkv, bqkv, nullptr);
    // Pass 1: per-key-column softmax stats (S recomputed on tensor cores)
    stats_kernel2<<<dim3(8, BHn), 256, P1_SMEM>>>();
    // Pass 2: fused attention (no P materialization)
    attn_kernel2<<<dim3(8, BHn), 256, P2_SMEM>>>();
    // K5: output projection
    gemm_rr_kernel<Cc, 0><<<dim3(MT / 128, Cc / 128), 256>>>(nullptr, Wproj, bproj, out);
}

// round 4
// speedup vs baseline: 1.9228x; 1.7172x over previous
#include <cuda_runtime.h>
#include <cuda_fp16.h>
#include <stdint.h>

#define DI __device__ __forceinline__

// Problem constants
constexpr int Bb = 8, Ls = 1024, Cc = 1024, Hh = 16, Dd = 64;
constexpr int BHn = Bb * Hh;      // 128
constexpr int MT  = Bb * Ls;      // 8192 tokens
constexpr int NQKV = 3 * Cc;      // 3072

// Scratch (device globals: allocation-free per harness rules). All half now.
__device__ __half g_Q[BHn * Ls * Dd];         // 16 MB  (b,h,l,d)
__device__ __half g_K[BHn * Ls * Dd];         // 16 MB
__device__ __half g_V[BHn * Ls * Dd];         // 16 MB
__device__ float  g_Mx[BHn * Ls];             // per-(bh,j) column max
__device__ float  g_Zi[BHn * Ls];             // per-(bh,j) 1/sum(exp)
__device__ __half g_Y[MT * Cc];               // 16 MB  (b,l,c) attention output

// ---------------------------------------------------------------------------
// helpers
// ---------------------------------------------------------------------------
DI unsigned pack2(float a, float b) {
    __half2 h = __floats2half2_rn(a, b);
    return *(unsigned*)&h;
}
DI unsigned s2u(const void* p) { return (unsigned)__cvta_generic_to_shared(p); }

DI void ldsm4(unsigned r[4], unsigned a) {
    asm volatile("ldmatrix.sync.aligned.m8n8.x4.shared.b16 {%0,%1,%2,%3}, [%4];"
                 : "=r"(r[0]), "=r"(r[1]), "=r"(r[2]), "=r"(r[3]) : "r"(a));
}
DI void ldsm4t(unsigned r[4], unsigned a) {
    asm volatile("ldmatrix.sync.aligned.m8n8.x4.trans.shared.b16 {%0,%1,%2,%3}, [%4];"
                 : "=r"(r[0]), "=r"(r[1]), "=r"(r[2]), "=r"(r[3]) : "r"(a));
}

DI void mma16(float c[4], const unsigned a[4], const unsigned b[2]) {
    asm volatile(
        "mma.sync.aligned.m16n8k16.row.col.f32.f16.f16.f32 "
        "{%0,%1,%2,%3}, {%4,%5,%6,%7}, {%8,%9}, {%0,%1,%2,%3};"
        : "+f"(c[0]), "+f"(c[1]), "+f"(c[2]), "+f"(c[3])
        : "r"(a[0]), "r"(a[1]), "r"(a[2]), "r"(a[3]), "r"(b[0]), "r"(b[1]));
}

DI void onl(float& m, float& z, float x) {
    if (x > m) {
        z = z * __expf(m - x) + 1.f;
        m = x;
    } else {
        z += __expf(x - m);
    }
}

// ---------------------------------------------------------------------------
// K1 / K5: C = A(MxK) * B(KxN) + bias.  128x128 tile, BK=32, 256 thr, fp16 mma.
// EPI==1: A = x (fp32), scatter half results into g_Q/g_K/g_V per-head layout
// EPI==0: A = g_Y (half), write fp32 to Cout
// ---------------------------------------------------------------------------
template <int NC, int EPI>
__global__ void __launch_bounds__(256, 2)
gemm_rr_kernel(const float* __restrict__ A, const float* __restrict__ Bm,
               const float* __restrict__ bias, float* __restrict__ Cout) {
    __shared__ __half As[128][40];    // [m][k]  stride 40 halfs = 80 B
    __shared__ __half Bs[32][136];    // [k][n]  stride 136 halfs = 272 B

    const int t  = threadIdx.x;
    const int m0 = blockIdx.x * 128, n0 = blockIdx.y * 128;
    constexpr int K  = Cc;            // 1024
    constexpr int NK = K / 32;        // 32

    const int lane = t & 31, wid = t >> 5;
    const int lr = lane >> 2, lc = lane & 3;
    const int wm = (wid >> 2) * 64, wn = (wid & 3) * 32;

    // loader indices
    const int ar = t >> 3, ac = (t & 7) * 4;   // EPI1 A loader (fp32 x)
    const int yr = t & 127, yk = (t >> 7) * 16; // EPI0 A loader (half g_Y)
    const int br = t >> 5, bc = (t & 31) * 4;  // B loader (fp32 W)

    // ldmatrix per-lane address bases
    const int qrow = (lane & 7) + ((lane >> 3) & 1) * 8;
    const int qcol = (lane >> 4) * 8;
    const unsigned Abase = s2u(&As[0][0]) + ((wm + qrow) * 40 + qcol) * 2;
    const unsigned Bbase = s2u(&Bs[0][0]) + (qrow * 136 + wn + qcol) * 2;

    float acc[4][4][4];
#pragma unroll
    for (int i = 0; i < 4; i++)
#pragma unroll
        for (int j = 0; j < 4; j++)
#pragma unroll
            for (int k = 0; k < 4; k++) acc[i][j][k] = 0.f;

    float4 ra[4], rb[4];
    uint4 ya[2];

    // prologue: load kt=0 into regs
    if (EPI == 1) {
#pragma unroll
        for (int i = 0; i < 4; i++)
            ra[i] = *(const float4*)(A + (size_t)(m0 + ar + i * 32) * K + ac);
    } else {
        const __half* Yp = g_Y + (size_t)(m0 + yr) * K;
        ya[0] = *(const uint4*)(Yp + yk);
        ya[1] = *(const uint4*)(Yp + yk + 8);
    }
#pragma unroll
    for (int i = 0; i < 4; i++)
        rb[i] = *(const float4*)(Bm + (size_t)(br + i * 8) * NC + n0 + bc);

#pragma unroll 1
    for (int kt = 0; kt < NK; kt++) {
        // store staged regs -> smem (half)
        if (EPI == 1) {
#pragma unroll
            for (int i = 0; i < 4; i++) {
                float4 v = ra[i];
                *(uint2*)&As[ar + i * 32][ac] =
                    make_uint2(pack2(v.x, v.y), pack2(v.z, v.w));
            }
        } else {
            *(uint4*)&As[yr][yk]     = ya[0];
            *(uint4*)&As[yr][yk + 8] = ya[1];
        }
#pragma unroll
        for (int i = 0; i < 4; i++) {
            float4 v = rb[i];
            *(uint2*)&Bs[br + i * 8][bc] =
                make_uint2(pack2(v.x, v.y), pack2(v.z, v.w));
        }
        __syncthreads();

        if (kt + 1 < NK) {
            int kk = (kt + 1) * 32;
            if (EPI == 1) {
#pragma unroll
                for (int i = 0; i < 4; i++)
                    ra[i] = *(const float4*)(A + (size_t)(m0 + ar + i * 32) * K + kk + ac);
            } else {
                const __half* Yp = g_Y + (size_t)(m0 + yr) * K + kk;
                ya[0] = *(const uint4*)(Yp + yk);
                ya[1] = *(const uint4*)(Yp + yk + 8);
            }
#pragma unroll
            for (int i = 0; i < 4; i++)
                rb[i] = *(const float4*)(Bm + (size_t)(kk + br + i * 8) * NC + n0 + bc);
        }

#pragma unroll
        for (int ks = 0; ks < 2; ks++) {
            unsigned af[4][4], bq[2][4];
#pragma unroll
            for (int im = 0; im < 4; im++) ldsm4(af[im], Abase + im * 16 * 80 + ks * 32);
#pragma unroll
            for (int np = 0; np < 2; np++) ldsm4t(bq[np], Bbase + ks * 16 * 272 + np * 32);
#pragma unroll
            for (int im = 0; im < 4; im++) {
                mma16(acc[im][0], af[im], &bq[0][0]);
                mma16(acc[im][1], af[im], &bq[0][2]);
                mma16(acc[im][2], af[im], &bq[1][0]);
                mma16(acc[im][3], af[im], &bq[1][2]);
            }
        }
        __syncthreads();
    }

    // epilogue
#pragma unroll
    for (int im = 0; im < 4; im++) {
#pragma unroll
        for (int in_ = 0; in_ < 4; in_++) {
            int r0 = m0 + wm + im * 16 + lr;
            int c0 = n0 + wn + in_ * 8 + lc * 2;
            float bz0 = bias[c0], bz1 = bias[c0 + 1];
#pragma unroll
            for (int h2 = 0; h2 < 2; h2++) {
                int r = r0 + h2 * 8;
                float v0 = acc[im][in_][h2 * 2 + 0] + bz0;
                float v1 = acc[im][in_][h2 * 2 + 1] + bz1;
                if (EPI == 0) {
                    *(float2*)&Cout[(size_t)r * NC + c0] = make_float2(v0, v1);
                } else {
                    int sec = c0 >> 10, w = c0 & 1023;
                    int hh = w >> 6, dd = w & 63;
                    int bi = r >> 10, li = r & 1023;
                    __half* dst = (sec == 0) ? g_Q : (sec == 1) ? g_K : g_V;
                    *(__half2*)&dst[(((size_t)(bi * Hh + hh)) * Ls + li) * Dd + dd] =
                        __floats2half2_rn(v0, v1);
                }
            }
        }
    }
}

// ---------------------------------------------------------------------------
// Pass 1: per-key-column softmax stats, S recomputed with fp16 mma.
// CTA = (jt, bh). K-frags in regs; Q tiles streamed.  Tiles stride 72 halfs.
// ---------------------------------------------------------------------------
__global__ void __launch_bounds__(256, 2) stats_kernel2() {
    __shared__ __half Ksm[128][72];
    __shared__ __half Qsm[128][72];

    const int jt = blockIdx.x, bh = blockIdx.y;
    const int t = threadIdx.x;
    const int lane = t & 31, wid = t >> 5;
    const int lr = lane >> 2, lc = lane & 3;
    const int wm = wid * 16;
    const int tr = t >> 3, tc = (t & 7) * 8;   // tile loader: 16B chunks

    const __half* Kp = g_K + ((size_t)bh * Ls + jt * 128) * Dd;
    const __half* Qp = g_Q + (size_t)bh * Ls * Dd;

    // load K tile
#pragma unroll
    for (int i = 0; i < 4; i++) {
        int r = tr + 32 * i;
        *(uint4*)&Ksm[r][tc] = *(const uint4*)(Kp + (size_t)r * Dd + tc);
    }
    // prefetch first Q tile
    uint4 rq[4];
#pragma unroll
    for (int i = 0; i < 4; i++) {
        int r = tr + 32 * i;
        rq[i] = *(const uint4*)(Qp + (size_t)(jt * 128 + r) * Dd + tc);
    }
    __syncthreads();

    // K fragments (A operand) for whole kernel: 4 k16 steps over D=64
    unsigned af[4][4];
#pragma unroll
    for (int ks = 0; ks < 4; ks++) {
        int k = ks * 16 + lc * 2;
        af[ks][0] = *(unsigned*)&Ksm[wm + lr][k];
        af[ks][1] = *(unsigned*)&Ksm[wm + lr + 8][k];
        af[ks][2] = *(unsigned*)&Ksm[wm + lr][k + 8];
        af[ks][3] = *(unsigned*)&Ksm[wm + lr + 8][k + 8];
    }

    float m0 = -3e38f, z0 = 0.f, m1 = -3e38f, z1 = 0.f;
    const int j0 = jt * 128 + wm + lr;
    const int j1 = j0 + 8;

    for (int it = jt; it < 8; it++) {
#pragma unroll
        for (int i = 0; i < 4; i++) {
            int r = tr + 32 * i;
            *(uint4*)&Qsm[r][tc] = rq[i];
        }
        __syncthreads();
        if (it + 1 < 8) {
#pragma unroll
            for (int i = 0; i < 4; i++) {
                int r = tr + 32 * i;
                rq[i] = *(const uint4*)(Qp + (size_t)((it + 1) * 128 + r) * Dd + tc);
            }
        }
        const bool diag = (it == jt);
#pragma unroll
        for (int nt = 0; nt < 16; nt++) {
            float acc[4] = {0.f, 0.f, 0.f, 0.f};
#pragma unroll
            for (int ks = 0; ks < 4; ks++) {
                int k = ks * 16 + lc * 2;
                unsigned bf[2];
                bf[0] = *(unsigned*)&Qsm[nt * 8 + lr][k];
                bf[1] = *(unsigned*)&Qsm[nt * 8 + lr][k + 8];
                mma16(acc, af[ks], bf);
            }
            int i0 = it * 128 + nt * 8 + lc * 2;
            if (!diag || i0 >= j0)     onl(m0, z0, acc[0] * 0.125f);
            if (!diag || i0 + 1 >= j0) onl(m0, z0, acc[1] * 0.125f);
            if (!diag || i0 >= j1)     onl(m1, z1, acc[2] * 0.125f);
            if (!diag || i0 + 1 >= j1) onl(m1, z1, acc[3] * 0.125f);
        }
        __syncthreads();
    }

    // reduce across the 4 lanes sharing a row
#pragma unroll
    for (int off = 1; off <= 2; off <<= 1) {
        float mo = __shfl_xor_sync(0xFFFFFFFFu, m0, off);
        float zo = __shfl_xor_sync(0xFFFFFFFFu, z0, off);
        if (mo > m0) { z0 = z0 * __expf(m0 - mo) + zo; m0 = mo; }
        else         { z0 += zo * __expf(mo - m0); }
        mo = __shfl_xor_sync(0xFFFFFFFFu, m1, off);
        zo = __shfl_xor_sync(0xFFFFFFFFu, z1, off);
        if (mo > m1) { z1 = z1 * __expf(m1 - mo) + zo; m1 = mo; }
        else         { z1 += zo * __expf(mo - m1); }
    }
    if (lc == 0) {
        g_Mx[bh * Ls + j0] = m0;
        g_Zi[bh * Ls + j0] = 1.f / z0;
        g_Mx[bh * Ls + j1] = m1;
        g_Zi[bh * Ls + j1] = 1.f / z1;
    }
}

// ---------------------------------------------------------------------------
// Pass 2: y[i,d] = sum_{j<=i} exp(s_ij - m_j)*Zi_j * v[j,d].  fp16 mma.
// smem halfs: Ws[128][136] | Ksm[128][72] | Vsm[128][72] | msm/zsm fp32
// V B-frags via ldmatrix.x4.trans ([j][d]-stored tile, k=j contiguity solved).
// ---------------------------------------------------------------------------
constexpr int AT_KS = 128 * 136;                  // 17408 halfs
constexpr int AT_VS = AT_KS + 128 * 72;           // 26624
constexpr int AT_HALFS = AT_VS + 128 * 72;        // 35840
constexpr int P2_SMEM = AT_HALFS * 2 + 2 * 128 * 4; // 71680 + 1024 = 72704 B

__global__ void __launch_bounds__(256, 2) attn_kernel2() {
    extern __shared__ __half smh[];
    __half* Ws  = smh;                 // [128][136]
    __half* Ksm = smh + AT_KS;         // [128][72]
    __half* Vsm = smh + AT_VS;         // [128][72]
    float* msm = (float*)(smh + AT_HALFS);
    float* zsm = msm + 128;

    const int it = 7 - blockIdx.x;     // heavy tiles first
    const int bh = blockIdx.y;
    const int b = bh >> 4, h = bh & 15;
    const int t = threadIdx.x;
    const int lane = t & 31, wid = t >> 5;
    const int lr = lane >> 2, lc = lane & 3;
    const int wm = wid * 16;
    const int tr = t >> 3, tc = (t & 7) * 8;

    const __half* Qp = g_Q + ((size_t)bh * Ls + it * 128) * Dd;
    const __half* Kp = g_K + (size_t)bh * Ls * Dd;
    const __half* Vp = g_V + (size_t)bh * Ls * Dd;

    // V ldmatrix per-lane base (rows stride 72 halfs = 144 B)
    const int vrow = (lane & 7) + ((lane >> 3) & 1) * 8;
    const int vcol = (lane >> 4) * 8;
    const unsigned Vbase = s2u(Vsm) + (vrow * 72 + vcol) * 2;

    // stage Q into Ksm, read fragments
#pragma unroll
    for (int i = 0; i < 4; i++) {
        int r = tr + 32 * i;
        *(uint4*)&Ksm[(size_t)r * 72 + tc] = *(const uint4*)(Qp + (size_t)r * Dd + tc);
    }
    __syncthreads();
    unsigned qf[4][4];
#pragma unroll
    for (int ks = 0; ks < 4; ks++) {
        int k = ks * 16 + lc * 2;
        qf[ks][0] = *(unsigned*)&Ksm[(wm + lr) * 72 + k];
        qf[ks][1] = *(unsigned*)&Ksm[(wm + lr + 8) * 72 + k];
        qf[ks][2] = *(unsigned*)&Ksm[(wm + lr) * 72 + k + 8];
        qf[ks][3] = *(unsigned*)&Ksm[(wm + lr + 8) * 72 + k + 8];
    }

    float yacc[8][4];
#pragma unroll
    for (int i = 0; i < 8; i++)
#pragma unroll
        for (int q = 0; q < 4; q++) yacc[i][q] = 0.f;

    // prefetch tile 0
    uint4 rk[4], rv[4];
    float rstat;
#pragma unroll
    for (int i = 0; i < 4; i++) {
        int r = tr + 32 * i;
        rk[i] = *(const uint4*)(Kp + (size_t)r * Dd + tc);
        rv[i] = *(const uint4*)(Vp + (size_t)r * Dd + tc);
    }
    rstat = (t < 128) ? g_Mx[bh * Ls + t] : g_Zi[bh * Ls + (t - 128)];

    const int i0r = it * 128 + wm + lr;
    const int i1r = i0r + 8;

#pragma unroll 1
    for (int kt = 0; kt <= it; kt++) {
        __syncthreads();   // prior GEMM2 / qf reads complete
#pragma unroll
        for (int i = 0; i < 4; i++) {
            int r = tr + 32 * i;
            *(uint4*)&Ksm[(size_t)r * 72 + tc] = rk[i];
            *(uint4*)&Vsm[(size_t)r * 72 + tc] = rv[i];
        }
        if (t < 128) msm[t] = rstat; else zsm[t - 128] = rstat;
        __syncthreads();

        if (kt < it) {
            int roff = (kt + 1) * 128;
#pragma unroll
            for (int i = 0; i < 4; i++) {
                int r = roff + tr + 32 * i;
                rk[i] = *(const uint4*)(Kp + (size_t)r * Dd + tc);
                rv[i] = *(const uint4*)(Vp + (size_t)r * Dd + tc);
            }
            rstat = (t < 128) ? g_Mx[bh * Ls + roff + t]
                              : g_Zi[bh * Ls + roff + (t - 128)];
        }

        const bool diag = (kt == it);
        // GEMM1: S tile (16 rows/warp x 128 j) + softmax weights -> Ws
#pragma unroll
        for (int nt = 0; nt < 16; nt++) {
            float acc[4] = {0.f, 0.f, 0.f, 0.f};
#pragma unroll
            for (int ks = 0; ks < 4; ks++) {
                int k = ks * 16 + lc * 2;
                unsigned bf[2];
                bf[0] = *(unsigned*)&Ksm[(nt * 8 + lr) * 72 + k];
                bf[1] = *(unsigned*)&Ksm[(nt * 8 + lr) * 72 + k + 8];
                mma16(acc, qf[ks], bf);
            }
            int jl = nt * 8 + lc * 2;
            float mj0 = msm[jl], zj0 = zsm[jl];
            float mj1 = msm[jl + 1], zj1 = zsm[jl + 1];
            float w00 = __expf(acc[0] * 0.125f - mj0) * zj0;
            float w01 = __expf(acc[1] * 0.125f - mj1) * zj1;
            float w10 = __expf(acc[2] * 0.125f - mj0) * zj0;
            float w11 = __expf(acc[3] * 0.125f - mj1) * zj1;
            if (diag) {
                int jg = kt * 128 + jl;
                if (i0r < jg)     w00 = 0.f;
                if (i0r < jg + 1) w01 = 0.f;
                if (i1r < jg)     w10 = 0.f;
                if (i1r < jg + 1) w11 = 0.f;
            }
            *(unsigned*)&Ws[(wm + lr) * 136 + jl]     = pack2(w00, w01);
            *(unsigned*)&Ws[(wm + lr + 8) * 136 + jl] = pack2(w10, w11);
        }
        __syncwarp();   // warp-private Ws rows

        // GEMM2: Y += Ws x V  (k = j, 8 k16 steps; V frags via ldmatrix.trans)
#pragma unroll
        for (int ks = 0; ks < 8; ks++) {
            int k = ks * 16 + lc * 2;
            unsigned a2[4];
            a2[0] = *(unsigned*)&Ws[(wm + lr) * 136 + k];
            a2[1] = *(unsigned*)&Ws[(wm + lr + 8) * 136 + k];
            a2[2] = *(unsigned*)&Ws[(wm + lr) * 136 + k + 8];
            a2[3] = *(unsigned*)&Ws[(wm + lr + 8) * 136 + k + 8];
#pragma unroll
            for (int dtp = 0; dtp < 4; dtp++) {
                unsigned bt[4];
                ldsm4t(bt, Vbase + ks * 16 * 144 + dtp * 32);
                mma16(yacc[dtp * 2],     a2, &bt[0]);
                mma16(yacc[dtp * 2 + 1], a2, &bt[2]);
            }
        }
    }

    // epilogue -> g_Y (b, l, c) half
#pragma unroll
    for (int dt = 0; dt < 8; dt++) {
        int d0 = dt * 8 + lc * 2;
        *(__half2*)&g_Y[((size_t)(b * Ls + i0r)) * Cc + h * Dd + d0] =
            __floats2half2_rn(yacc[dt][0], yacc[dt][1]);
        *(__half2*)&g_Y[((size_t)(b * Ls + i1r)) * Cc + h * Dd + d0] =
            __floats2half2_rn(yacc[dt][2], yacc[dt][3]);
    }
}

// ---------------------------------------------------------------------------
// Launch
// ---------------------------------------------------------------------------
extern "C" void kernel_launch(void* const* d_in, const int* in_sizes, int n_in,
                              void* d_out, int out_size) {
    const float* x     = (const float*)d_in[0];
    const float* Wqkv  = (const float*)d_in[1];
    const float* bqkv  = (const float*)d_in[2];
    const float* Wproj = (const float*)d_in[3];
    const float* bproj = (const float*)d_in[4];
    float* out = (float*)d_out;

    (void)cudaFuncSetAttribute(attn_kernel2,
                               cudaFuncAttributeMaxDynamicSharedMemorySize, P2_SMEM);

    // K1: QKV projection, scatter half into per-head Q/K/V
    gemm_rr_kernel<NQKV, 1><<<dim3(MT / 128, NQKV / 128), 256>>>(x, Wqkv, bqkv, nullptr);
    // Pass 1: per-key-column softmax stats
    stats_kernel2<<<dim3(8, BHn), 256>>>();
    // Pass 2: fused attention
    attn_kernel2<<<dim3(8, BHn), 256, P2_SMEM>>>();
    // K5: output projection (fp32 out)
    gemm_rr_kernel<Cc, 0><<<dim3(MT / 128, Cc / 128), 256>>>(nullptr, Wproj, bproj, out);
}

// round 8
// speedup vs baseline: 2.0447x; 1.0634x over previous
#include <cuda_runtime.h>
#include <cuda_fp16.h>
#include <stdint.h>

#define DI __device__ __forceinline__

// Problem constants
constexpr int Bb = 8, Ls = 1024, Cc = 1024, Hh = 16, Dd = 64;
constexpr int BHn = Bb * Hh;      // 128
constexpr int MT  = Bb * Ls;      // 8192 tokens
constexpr int NQKV = 3 * Cc;      // 3072

// Scratch (device globals: allocation-free per harness rules)
__device__ __half g_Q[BHn * Ls * Dd];         // 16 MB  (b,h,l,d)
__device__ __half g_K[BHn * Ls * Dd];         // 16 MB
__device__ __half g_V[BHn * Ls * Dd];         // 16 MB
__device__ float  g_Mx[BHn * Ls];
__device__ float  g_Zi[BHn * Ls];
__device__ __half g_Y[MT * Cc];               // 16 MB  (b,l,c)
__device__ __half g_Xh[MT * Cc];              // 16 MB  x as half
__device__ __half g_Wqkvh[Cc * NQKV];         // 6 MB   W_qkv as half [K][N]
__device__ __half g_Wprojh[Cc * Cc];          // 2 MB   W_proj as half [K][N]

// ---------------------------------------------------------------------------
// helpers
// ---------------------------------------------------------------------------
DI unsigned pack2(float a, float b) {
    __half2 h = __floats2half2_rn(a, b);
    return *(unsigned*)&h;
}
DI unsigned s2u(const void* p) { return (unsigned)__cvta_generic_to_shared(p); }

DI void ldsm4(unsigned r[4], unsigned a) {
    asm volatile("ldmatrix.sync.aligned.m8n8.x4.shared.b16 {%0,%1,%2,%3}, [%4];"
                 : "=r"(r[0]), "=r"(r[1]), "=r"(r[2]), "=r"(r[3]) : "r"(a));
}
DI void ldsm4t(unsigned r[4], unsigned a) {
    asm volatile("ldmatrix.sync.aligned.m8n8.x4.trans.shared.b16 {%0,%1,%2,%3}, [%4];"
                 : "=r"(r[0]), "=r"(r[1]), "=r"(r[2]), "=r"(r[3]) : "r"(a));
}
DI void mma16(float c[4], const unsigned a[4], const unsigned b[2]) {
    asm volatile(
        "mma.sync.aligned.m16n8k16.row.col.f32.f16.f16.f32 "
        "{%0,%1,%2,%3}, {%4,%5,%6,%7}, {%8,%9}, {%0,%1,%2,%3};"
        : "+f"(c[0]), "+f"(c[1]), "+f"(c[2]), "+f"(c[3])
        : "r"(a[0]), "r"(a[1]), "r"(a[2]), "r"(a[3]), "r"(b[0]), "r"(b[1]));
}
DI void cp16(unsigned dst, const void* src) {
    asm volatile("cp.async.cg.shared.global [%0], [%1], 16;" :: "r"(dst), "l"(src) : "memory");
}
DI void cp_commit() { asm volatile("cp.async.commit_group;" ::: "memory"); }
template <int N> DI void cp_wait() {
    asm volatile("cp.async.wait_group %0;" :: "n"(N) : "memory");
}
DI void onl(float& m, float& z, float x) {
    if (x > m) { z = z * __expf(m - x) + 1.f; m = x; }
    else       { z += __expf(x - m); }
}

// ---------------------------------------------------------------------------
// Pre-pass: fp32 -> half elementwise (x, W_qkv, W_proj)
// ---------------------------------------------------------------------------
__global__ void conv_kernel(const float* __restrict__ src, __half* __restrict__ dst) {
    size_t i = ((size_t)blockIdx.x * 256 + threadIdx.x) * 4;
    float4 v = *(const float4*)(src + i);
    *(uint2*)(dst + i) = make_uint2(pack2(v.x, v.y), pack2(v.z, v.w));
}

// ---------------------------------------------------------------------------
// Big-tile GEMM: C[128x256] = A[M][1024] * B[1024][NC] + bias.
// A,B half in GMEM. 8 warps, 64x64 warp tiles, BK=32, 4-stage cp.async.
// EPI==1: scatter half into g_Q/g_K/g_V per-head layout (QKV)
// EPI==0: fp32 out to Cout (proj)
// smem: [0..1024) bias fp32 | stages at 1024 + s*27136:
//       A [128][40] half (10240 B) then B [32][264] half (16896 B)
// ---------------------------------------------------------------------------
constexpr int STG_BYTES = 27136;
constexpr int GB_SMEM = 1024 + 4 * STG_BYTES;   // 109568 B

template <int NC, int EPI>
__global__ void __launch_bounds__(256, 1)
gemm_big(const __half* __restrict__ Ah, const __half* __restrict__ Bh,
         const float* __restrict__ bias, float* __restrict__ Cout) {
    extern __shared__ char sm[];
    float* bsm = (float*)sm;
    const unsigned sbase = s2u(sm);

    const int t = threadIdx.x, lane = t & 31, wid = t >> 5;
    const int m0 = blockIdx.x * 128, n0 = blockIdx.y * 256;
    const int wm = (wid >> 2) * 64, wn = (wid & 3) * 64;
    const int lr = lane >> 2, lc = lane & 3;

    bsm[t] = bias[n0 + t];

    // loader geometry
    const int arow = t >> 2, ac8 = (t & 3) * 8;    // A rows arow, arow+64
    const int brow = t >> 3, bc8 = (t & 7) * 8;    // B row brow, 4 col chunks

    const __half* agp  = Ah + (size_t)(m0 + arow) * 1024 + ac8;
    const __half* agp2 = agp + (size_t)64 * 1024;
    const __half* bgp  = Bh + (size_t)brow * NC + n0 + bc8;

    const unsigned as_st = sbase + 1024 + (arow * 40 + ac8) * 2;
    const unsigned as_st2 = sbase + 1024 + ((arow + 64) * 40 + ac8) * 2;
    const unsigned bs_st = sbase + 1024 + 10240 + (brow * 264 + bc8) * 2;

    // ldmatrix per-lane geometry
    const int qrow = (lane & 7) + ((lane >> 3) & 1) * 8;
    const int qcol = (lane >> 4) * 8;
    const unsigned a_frag = sbase + 1024 + ((wm + qrow) * 40 + qcol) * 2;
    const unsigned b_frag = sbase + 1024 + 10240 + (qrow * 264 + wn + qcol) * 2;

    float acc[4][8][4];
#pragma unroll
    for (int i = 0; i < 4; i++)
#pragma unroll
        for (int j = 0; j < 8; j++)
#pragma unroll
            for (int q = 0; q < 4; q++) acc[i][j][q] = 0.f;

    // B chunks live at smem col offsets 0,64,128,192 halfs = +0,+128,+256,+384 B
#define ISSUE(kt)                                                          \
    do {                                                                   \
        const int s_ = (kt) & 3;                                           \
        const unsigned so_ = s_ * STG_BYTES;                               \
        cp16(as_st + so_, agp + (kt) * 32);                                \
        cp16(as_st2 + so_, agp2 + (kt) * 32);                              \
        const __half* bk_ = bgp + (size_t)(kt) * 32 * NC;                  \
        cp16(bs_st + so_, bk_);                                            \
        cp16(bs_st + so_ + 128, bk_ + 64);                                 \
        cp16(bs_st + so_ + 256, bk_ + 128);                                \
        cp16(bs_st + so_ + 384, bk_ + 192);                                \
        cp_commit();                                                       \
    } while (0)

    ISSUE(0); ISSUE(1); ISSUE(2);

#pragma unroll 1
    for (int kt = 0; kt < 32; kt++) {
        cp_wait<2>();
        __syncthreads();
        if (kt + 3 < 32) ISSUE(kt + 3);
        const unsigned so = (kt & 3) * STG_BYTES;
#pragma unroll
        for (int ks = 0; ks < 2; ks++) {
            unsigned af[4][4], bq[4][4];
#pragma unroll
            for (int im = 0; im < 4; im++)
                ldsm4(af[im], a_frag + so + im * 16 * 80 + ks * 32);
#pragma unroll
            for (int np = 0; np < 4; np++)
                ldsm4t(bq[np], b_frag + so + ks * 16 * 528 + np * 32);
#pragma unroll
            for (int im = 0; im < 4; im++)
#pragma unroll
                for (int np = 0; np < 4; np++) {
                    mma16(acc[im][np * 2],     af[im], &bq[np][0]);
                    mma16(acc[im][np * 2 + 1], af[im], &bq[np][2]);
                }
        }
    }
#undef ISSUE

    // epilogue
#pragma unroll
    for (int im = 0; im < 4; im++) {
#pragma unroll
        for (int j = 0; j < 8; j++) {
            int r0 = m0 + wm + im * 16 + lr;
            int c0 = wn + j * 8 + lc * 2;            // 0..255 within tile
            float bz0 = bsm[c0], bz1 = bsm[c0 + 1];
            int gc = n0 + c0;
#pragma unroll
            for (int h2 = 0; h2 < 2; h2++) {
                int r = r0 + h2 * 8;
                float v0 = acc[im][j][h2 * 2 + 0] + bz0;
                float v1 = acc[im][j][h2 * 2 + 1] + bz1;
                if (EPI == 0) {
                    *(float2*)&Cout[(size_t)r * NC + gc] = make_float2(v0, v1);
                } else {
                    int sec = gc >> 10, w = gc & 1023;
                    int hh = w >> 6, dd = w & 63;
                    int bi = r >> 10, li = r & 1023;
                    __half* dst = (sec == 0) ? g_Q : (sec == 1) ? g_K : g_V;
                    *(__half2*)&dst[(((size_t)(bi * Hh + hh)) * Ls + li) * Dd + dd] =
                        __floats2half2_rn(v0, v1);
                }
            }
        }
    }
}

// ---------------------------------------------------------------------------
// Pass 1: per-key-column softmax stats (unchanged)
// ---------------------------------------------------------------------------
__global__ void __launch_bounds__(256, 2) stats_kernel2() {
    __shared__ __half Ksm[128][72];
    __shared__ __half Qsm[128][72];

    const int jt = blockIdx.x, bh = blockIdx.y;
    const int t = threadIdx.x;
    const int lane = t & 31, wid = t >> 5;
    const int lr = lane >> 2, lc = lane & 3;
    const int wm = wid * 16;
    const int tr = t >> 3, tc = (t & 7) * 8;

    const __half* Kp = g_K + ((size_t)bh * Ls + jt * 128) * Dd;
    const __half* Qp = g_Q + (size_t)bh * Ls * Dd;

#pragma unroll
    for (int i = 0; i < 4; i++) {
        int r = tr + 32 * i;
        *(uint4*)&Ksm[r][tc] = *(const uint4*)(Kp + (size_t)r * Dd + tc);
    }
    uint4 rq[4];
#pragma unroll
    for (int i = 0; i < 4; i++) {
        int r = tr + 32 * i;
        rq[i] = *(const uint4*)(Qp + (size_t)(jt * 128 + r) * Dd + tc);
    }
    __syncthreads();

    unsigned af[4][4];
#pragma unroll
    for (int ks = 0; ks < 4; ks++) {
        int k = ks * 16 + lc * 2;
        af[ks][0] = *(unsigned*)&Ksm[wm + lr][k];
        af[ks][1] = *(unsigned*)&Ksm[wm + lr + 8][k];
        af[ks][2] = *(unsigned*)&Ksm[wm + lr][k + 8];
        af[ks][3] = *(unsigned*)&Ksm[wm + lr + 8][k + 8];
    }

    float m0 = -3e38f, z0 = 0.f, m1 = -3e38f, z1 = 0.f;
    const int j0 = jt * 128 + wm + lr;
    const int j1 = j0 + 8;

    for (int it = jt; it < 8; it++) {
#pragma unroll
        for (int i = 0; i < 4; i++) {
            int r = tr + 32 * i;
            *(uint4*)&Qsm[r][tc] = rq[i];
        }
        __syncthreads();
        if (it + 1 < 8) {
#pragma unroll
            for (int i = 0; i < 4; i++) {
                int r = tr + 32 * i;
                rq[i] = *(const uint4*)(Qp + (size_t)((it + 1) * 128 + r) * Dd + tc);
            }
        }
        const bool diag = (it == jt);
#pragma unroll
        for (int nt = 0; nt < 16; nt++) {
            float acc[4] = {0.f, 0.f, 0.f, 0.f};
#pragma unroll
            for (int ks = 0; ks < 4; ks++) {
                int k = ks * 16 + lc * 2;
                unsigned bf[2];
                bf[0] = *(unsigned*)&Qsm[nt * 8 + lr][k];
                bf[1] = *(unsigned*)&Qsm[nt * 8 + lr][k + 8];
                mma16(acc, af[ks], bf);
            }
            int i0 = it * 128 + nt * 8 + lc * 2;
            if (!diag || i0 >= j0)     onl(m0, z0, acc[0] * 0.125f);
            if (!diag || i0 + 1 >= j0) onl(m0, z0, acc[1] * 0.125f);
            if (!diag || i0 >= j1)     onl(m1, z1, acc[2] * 0.125f);
            if (!diag || i0 + 1 >= j1) onl(m1, z1, acc[3] * 0.125f);
        }
        __syncthreads();
    }

#pragma unroll
    for (int off = 1; off <= 2; off <<= 1) {
        float mo = __shfl_xor_sync(0xFFFFFFFFu, m0, off);
        float zo = __shfl_xor_sync(0xFFFFFFFFu, z0, off);
        if (mo > m0) { z0 = z0 * __expf(m0 - mo) + zo; m0 = mo; }
        else         { z0 += zo * __expf(mo - m0); }
        mo = __shfl_xor_sync(0xFFFFFFFFu, m1, off);
        zo = __shfl_xor_sync(0xFFFFFFFFu, z1, off);
        if (mo > m1) { z1 = z1 * __expf(m1 - mo) + zo; m1 = mo; }
        else         { z1 += zo * __expf(mo - m1); }
    }
    if (lc == 0) {
        g_Mx[bh * Ls + j0] = m0;
        g_Zi[bh * Ls + j0] = 1.f / z0;
        g_Mx[bh * Ls + j1] = m1;
        g_Zi[bh * Ls + j1] = 1.f / z1;
    }
}

// ---------------------------------------------------------------------------
// Pass 2: fused attention (unchanged)
// ---------------------------------------------------------------------------
constexpr int AT_KS = 128 * 136;
constexpr int AT_VS = AT_KS + 128 * 72;
constexpr int AT_HALFS = AT_VS + 128 * 72;
constexpr int P2_SMEM = AT_HALFS * 2 + 2 * 128 * 4;   // 72704 B

__global__ void __launch_bounds__(256, 2) attn_kernel2() {
    extern __shared__ __half smh[];
    __half* Ws  = smh;
    __half* Ksm = smh + AT_KS;
    __half* Vsm = smh + AT_VS;
    float* msm = (float*)(smh + AT_HALFS);
    float* zsm = msm + 128;

    const int it = 7 - blockIdx.x;
    const int bh = blockIdx.y;
    const int b = bh >> 4, h = bh & 15;
    const int t = threadIdx.x;
    const int lane = t & 31, wid = t >> 5;
    const int lr = lane >> 2, lc = lane & 3;
    const int wm = wid * 16;
    const int tr = t >> 3, tc = (t & 7) * 8;

    const __half* Qp = g_Q + ((size_t)bh * Ls + it * 128) * Dd;
    const __half* Kp = g_K + (size_t)bh * Ls * Dd;
    const __half* Vp = g_V + (size_t)bh * Ls * Dd;

    const int vrow = (lane & 7) + ((lane >> 3) & 1) * 8;
    const int vcol = (lane >> 4) * 8;
    const unsigned Vbase = s2u(Vsm) + (vrow * 72 + vcol) * 2;

#pragma unroll
    for (int i = 0; i < 4; i++) {
        int r = tr + 32 * i;
        *(uint4*)&Ksm[(size_t)r * 72 + tc] = *(const uint4*)(Qp + (size_t)r * Dd + tc);
    }
    __syncthreads();
    unsigned qf[4][4];
#pragma unroll
    for (int ks = 0; ks < 4; ks++) {
        int k = ks * 16 + lc * 2;
        qf[ks][0] = *(unsigned*)&Ksm[(wm + lr) * 72 + k];
        qf[ks][1] = *(unsigned*)&Ksm[(wm + lr + 8) * 72 + k];
        qf[ks][2] = *(unsigned*)&Ksm[(wm + lr) * 72 + k + 8];
        qf[ks][3] = *(unsigned*)&Ksm[(wm + lr + 8) * 72 + k + 8];
    }

    float yacc[8][4];
#pragma unroll
    for (int i = 0; i < 8; i++)
#pragma unroll
        for (int q = 0; q < 4; q++) yacc[i][q] = 0.f;

    uint4 rk[4], rv[4];
    float rstat;
#pragma unroll
    for (int i = 0; i < 4; i++) {
        int r = tr + 32 * i;
        rk[i] = *(const uint4*)(Kp + (size_t)r * Dd + tc);
        rv[i] = *(const uint4*)(Vp + (size_t)r * Dd + tc);
    }
    rstat = (t < 128) ? g_Mx[bh * Ls + t] : g_Zi[bh * Ls + (t - 128)];

    const int i0r = it * 128 + wm + lr;
    const int i1r = i0r + 8;

#pragma unroll 1
    for (int kt = 0; kt <= it; kt++) {
        __syncthreads();
#pragma unroll
        for (int i = 0; i < 4; i++) {
            int r = tr + 32 * i;
            *(uint4*)&Ksm[(size_t)r * 72 + tc] = rk[i];
            *(uint4*)&Vsm[(size_t)r * 72 + tc] = rv[i];
        }
        if (t < 128) msm[t] = rstat; else zsm[t - 128] = rstat;
        __syncthreads();

        if (kt < it) {
            int roff = (kt + 1) * 128;
#pragma unroll
            for (int i = 0; i < 4; i++) {
                int r = roff + tr + 32 * i;
                rk[i] = *(const uint4*)(Kp + (size_t)r * Dd + tc);
                rv[i] = *(const uint4*)(Vp + (size_t)r * Dd + tc);
            }
            rstat = (t < 128) ? g_Mx[bh * Ls + roff + t]
                              : g_Zi[bh * Ls + roff + (t - 128)];
        }

        const bool diag = (kt == it);
#pragma unroll
        for (int nt = 0; nt < 16; nt++) {
            float acc[4] = {0.f, 0.f, 0.f, 0.f};
#pragma unroll
            for (int ks = 0; ks < 4; ks++) {
                int k = ks * 16 + lc * 2;
                unsigned bf[2];
                bf[0] = *(unsigned*)&Ksm[(nt * 8 + lr) * 72 + k];
                bf[1] = *(unsigned*)&Ksm[(nt * 8 + lr) * 72 + k + 8];
                mma16(acc, qf[ks], bf);
            }
            int jl = nt * 8 + lc * 2;
            float mj0 = msm[jl], zj0 = zsm[jl];
            float mj1 = msm[jl + 1], zj1 = zsm[jl + 1];
            float w00 = __expf(acc[0] * 0.125f - mj0) * zj0;
            float w01 = __expf(acc[1] * 0.125f - mj1) * zj1;
            float w10 = __expf(acc[2] * 0.125f - mj0) * zj0;
            float w11 = __expf(acc[3] * 0.125f - mj1) * zj1;
            if (diag) {
                int jg = kt * 128 + jl;
                if (i0r < jg)     w00 = 0.f;
                if (i0r < jg + 1) w01 = 0.f;
                if (i1r < jg)     w10 = 0.f;
                if (i1r < jg + 1) w11 = 0.f;
            }
            *(unsigned*)&Ws[(wm + lr) * 136 + jl]     = pack2(w00, w01);
            *(unsigned*)&Ws[(wm + lr + 8) * 136 + jl] = pack2(w10, w11);
        }
        __syncwarp();

#pragma unroll
        for (int ks = 0; ks < 8; ks++) {
            int k = ks * 16 + lc * 2;
            unsigned a2[4];
            a2[0] = *(unsigned*)&Ws[(wm + lr) * 136 + k];
            a2[1] = *(unsigned*)&Ws[(wm + lr + 8) * 136 + k];
            a2[2] = *(unsigned*)&Ws[(wm + lr) * 136 + k + 8];
            a2[3] = *(unsigned*)&Ws[(wm + lr + 8) * 136 + k + 8];
#pragma unroll
            for (int dtp = 0; dtp < 4; dtp++) {
                unsigned bt[4];
                ldsm4t(bt, Vbase + ks * 16 * 144 + dtp * 32);
                mma16(yacc[dtp * 2],     a2, &bt[0]);
                mma16(yacc[dtp * 2 + 1], a2, &bt[2]);
            }
        }
    }

#pragma unroll
    for (int dt = 0; dt < 8; dt++) {
        int d0 = dt * 8 + lc * 2;
        *(__half2*)&g_Y[((size_t)(b * Ls + i0r)) * Cc + h * Dd + d0] =
            __floats2half2_rn(yacc[dt][0], yacc[dt][1]);
        *(__half2*)&g_Y[((size_t)(b * Ls + i1r)) * Cc + h * Dd + d0] =
            __floats2half2_rn(yacc[dt][2], yacc[dt][3]);
    }
}

// ---------------------------------------------------------------------------
// Launch
// ---------------------------------------------------------------------------
extern "C" void kernel_launch(void* const* d_in, const int* in_sizes, int n_in,
                              void* d_out, int out_size) {
    const float* x     = (const float*)d_in[0];
    const float* Wqkv  = (const float*)d_in[1];
    const float* bqkv  = (const float*)d_in[2];
    const float* Wproj = (const float*)d_in[3];
    const float* bproj = (const float*)d_in[4];
    float* out = (float*)d_out;

    __half *xh, *wq, *wp, *yh;
    cudaGetSymbolAddress((void**)&xh, g_Xh);
    cudaGetSymbolAddress((void**)&wq, g_Wqkvh);
    cudaGetSymbolAddress((void**)&wp, g_Wprojh);
    cudaGetSymbolAddress((void**)&yh, g_Y);

    (void)cudaFuncSetAttribute(gemm_big<NQKV, 1>,
                               cudaFuncAttributeMaxDynamicSharedMemorySize, GB_SMEM);
    (void)cudaFuncSetAttribute(gemm_big<Cc, 0>,
                               cudaFuncAttributeMaxDynamicSharedMemorySize, GB_SMEM);
    (void)cudaFuncSetAttribute(attn_kernel2,
                               cudaFuncAttributeMaxDynamicSharedMemorySize, P2_SMEM);

    // pre-passes: fp32 -> half
    conv_kernel<<<MT * Cc / 1024, 256>>>(x, xh);
    conv_kernel<<<Cc * NQKV / 1024, 256>>>(Wqkv, wq);
    conv_kernel<<<Cc * Cc / 1024, 256>>>(Wproj, wp);

    // QKV projection, scatter half into per-head Q/K/V
    gemm_big<NQKV, 1><<<dim3(MT / 128, NQKV / 256), 256, GB_SMEM>>>(xh, wq, bqkv, nullptr);
    // softmax stats + fused attention
    stats_kernel2<<<dim3(8, BHn), 256>>>();
    attn_kernel2<<<dim3(8, BHn), 256, P2_SMEM>>>();
    // output projection (fp32 out)
    gemm_big<Cc, 0><<<dim3(MT / 128, Cc / 256), 256, GB_SMEM>>>(yh, wp, bproj, out);
}

// round 9
// speedup vs baseline: 2.1528x; 1.0529x over previous
#include <cuda_runtime.h>
#include <cuda_fp16.h>
#include <stdint.h>

#define DI __device__ __forceinline__

// Problem constants
constexpr int Bb = 8, Ls = 1024, Cc = 1024, Hh = 16, Dd = 64;
constexpr int BHn = Bb * Hh;      // 128
constexpr int MT  = Bb * Ls;      // 8192 tokens
constexpr int NQKV = 3 * Cc;      // 3072

// Scratch (device globals: allocation-free per harness rules)
__device__ __half g_Q[BHn * Ls * Dd];         // 16 MB  (b,h,l,d)
__device__ __half g_K[BHn * Ls * Dd];         // 16 MB
__device__ __half g_V[BHn * Ls * Dd];         // 16 MB
__device__ float  g_Mx[BHn * Ls];
__device__ float  g_Zi[BHn * Ls];
__device__ __half g_Y[MT * Cc];               // 16 MB  (b,l,c)
__device__ __half g_Xh[MT * Cc];              // 16 MB  x as half
__device__ __half g_Wqkvh[Cc * NQKV];         // 6 MB   W_qkv as half [K][N]
__device__ __half g_Wprojh[Cc * Cc];          // 2 MB   W_proj as half [K][N]

// ---------------------------------------------------------------------------
// helpers
// ---------------------------------------------------------------------------
DI unsigned pack2(float a, float b) {
    __half2 h = __floats2half2_rn(a, b);
    return *(unsigned*)&h;
}
DI unsigned s2u(const void* p) { return (unsigned)__cvta_generic_to_shared(p); }

DI void ldsm4(unsigned r[4], unsigned a) {
    asm volatile("ldmatrix.sync.aligned.m8n8.x4.shared.b16 {%0,%1,%2,%3}, [%4];"
                 : "=r"(r[0]), "=r"(r[1]), "=r"(r[2]), "=r"(r[3]) : "r"(a));
}
DI void ldsm4t(unsigned r[4], unsigned a) {
    asm volatile("ldmatrix.sync.aligned.m8n8.x4.trans.shared.b16 {%0,%1,%2,%3}, [%4];"
                 : "=r"(r[0]), "=r"(r[1]), "=r"(r[2]), "=r"(r[3]) : "r"(a));
}
DI void mma16(float c[4], const unsigned a[4], const unsigned b[2]) {
    asm volatile(
        "mma.sync.aligned.m16n8k16.row.col.f32.f16.f16.f32 "
        "{%0,%1,%2,%3}, {%4,%5,%6,%7}, {%8,%9}, {%0,%1,%2,%3};"
        : "+f"(c[0]), "+f"(c[1]), "+f"(c[2]), "+f"(c[3])
        : "r"(a[0]), "r"(a[1]), "r"(a[2]), "r"(a[3]), "r"(b[0]), "r"(b[1]));
}
DI void cp16(unsigned dst, const void* src) {
    asm volatile("cp.async.cg.shared.global [%0], [%1], 16;" :: "r"(dst), "l"(src) : "memory");
}
DI void cp_commit() { asm volatile("cp.async.commit_group;" ::: "memory"); }
template <int N> DI void cp_wait() {
    asm volatile("cp.async.wait_group %0;" :: "n"(N) : "memory");
}
DI void onl(float& m, float& z, float x) {
    if (x > m) { z = z * __expf(m - x) + 1.f; m = x; }
    else       { z += __expf(x - m); }
}

// ---------------------------------------------------------------------------
// Pre-pass: fp32 -> half elementwise (x, W_qkv, W_proj)
// ---------------------------------------------------------------------------
__global__ void conv_kernel(const float* __restrict__ src, __half* __restrict__ dst) {
    size_t i = ((size_t)blockIdx.x * 256 + threadIdx.x) * 4;
    float4 v = *(const float4*)(src + i);
    *(uint2*)(dst + i) = make_uint2(pack2(v.x, v.y), pack2(v.z, v.w));
}

// ---------------------------------------------------------------------------
// Big-tile GEMM v2: C[128x256] = A[M][1024] * B[1024][NC] + bias.
// 8 warps, 64x64 warp tiles, BK=64, 3-stage cp.async ring, 1 barrier/chunk.
// smem: [0..1024) bias | stage s at 1024 + s*52224:
//       A [128][72] half (18432 B) then B [64][264] half (33792 B)
// ---------------------------------------------------------------------------
constexpr int STG_A_BYTES = 128 * 72 * 2;       // 18432
constexpr int STG_BYTES   = STG_A_BYTES + 64 * 264 * 2;  // 52224
constexpr int GB_SMEM = 1024 + 3 * STG_BYTES;   // 157696 B

template <int NC, int EPI>
__global__ void __launch_bounds__(256, 1)
gemm_big(const __half* __restrict__ Ah, const __half* __restrict__ Bh,
         const float* __restrict__ bias, float* __restrict__ Cout) {
    extern __shared__ char sm[];
    float* bsm = (float*)sm;
    const unsigned sbase = s2u(sm);

    const int t = threadIdx.x, lane = t & 31, wid = t >> 5;
    const int m0 = blockIdx.x * 128, n0 = blockIdx.y * 256;
    const int wm = (wid >> 2) * 64, wn = (wid & 3) * 64;
    const int lr = lane >> 2, lc = lane & 3;

    bsm[t] = bias[n0 + t];

    // loader geometry: A 4 chunks (rows arow+32i), B 8 chunks (rows brow+8i)
    const int arow = t >> 3, acol = (t & 7) * 8;
    const int brow = t >> 5, bcol = (t & 31) * 8;

    const __half* agp = Ah + (size_t)(m0 + arow) * 1024 + acol;
    const __half* bgp = Bh + (size_t)brow * NC + n0 + bcol;

    const unsigned as_st = sbase + 1024 + (arow * 72 + acol) * 2;
    const unsigned bs_st = sbase + 1024 + STG_A_BYTES + (brow * 264 + bcol) * 2;

    // ldmatrix per-lane geometry
    const int qrow = (lane & 7) + ((lane >> 3) & 1) * 8;
    const int qcol = (lane >> 4) * 8;
    const unsigned a_frag = sbase + 1024 + ((wm + qrow) * 72 + qcol) * 2;
    const unsigned b_frag = sbase + 1024 + STG_A_BYTES + (qrow * 264 + wn + qcol) * 2;

    float acc[4][8][4];
#pragma unroll
    for (int i = 0; i < 4; i++)
#pragma unroll
        for (int j = 0; j < 8; j++)
#pragma unroll
            for (int q = 0; q < 4; q++) acc[i][j][q] = 0.f;

#define ISSUE(kt)                                                          \
    do {                                                                   \
        const unsigned so_ = ((kt) % 3) * STG_BYTES;                       \
        const __half* ag_ = agp + (size_t)(kt) * 64;                       \
        _Pragma("unroll")                                                  \
        for (int i_ = 0; i_ < 4; i_++)                                     \
            cp16(as_st + so_ + i_ * 32 * 144, ag_ + (size_t)(32 * i_) * 1024); \
        const __half* bg_ = bgp + (size_t)(kt) * 64 * NC;                  \
        _Pragma("unroll")                                                  \
        for (int i_ = 0; i_ < 8; i_++)                                     \
            cp16(bs_st + so_ + i_ * 8 * 528, bg_ + (size_t)(8 * i_) * NC); \
        cp_commit();                                                       \
    } while (0)

    ISSUE(0); ISSUE(1);

#pragma unroll 1
    for (int kt = 0; kt < 16; kt++) {
        cp_wait<1>();
        __syncthreads();
        if (kt + 2 < 16) ISSUE(kt + 2);
        const unsigned so = (kt % 3) * STG_BYTES;
#pragma unroll
        for (int ks = 0; ks < 4; ks++) {
            unsigned af[4][4], bq[4][4];
#pragma unroll
            for (int im = 0; im < 4; im++)
                ldsm4(af[im], a_frag + so + im * 16 * 144 + ks * 32);
#pragma unroll
            for (int np = 0; np < 4; np++)
                ldsm4t(bq[np], b_frag + so + ks * 16 * 528 + np * 32);
#pragma unroll
            for (int im = 0; im < 4; im++)
#pragma unroll
                for (int np = 0; np < 4; np++) {
                    mma16(acc[im][np * 2],     af[im], &bq[np][0]);
                    mma16(acc[im][np * 2 + 1], af[im], &bq[np][2]);
                }
        }
    }
#undef ISSUE

    // epilogue
#pragma unroll
    for (int im = 0; im < 4; im++) {
#pragma unroll
        for (int j = 0; j < 8; j++) {
            int r0 = m0 + wm + im * 16 + lr;
            int c0 = wn + j * 8 + lc * 2;
            float bz0 = bsm[c0], bz1 = bsm[c0 + 1];
            int gc = n0 + c0;
#pragma unroll
            for (int h2 = 0; h2 < 2; h2++) {
                int r = r0 + h2 * 8;
                float v0 = acc[im][j][h2 * 2 + 0] + bz0;
                float v1 = acc[im][j][h2 * 2 + 1] + bz1;
                if (EPI == 0) {
                    *(float2*)&Cout[(size_t)r * NC + gc] = make_float2(v0, v1);
                } else {
                    int sec = gc >> 10, w = gc & 1023;
                    int hh = w >> 6, dd = w & 63;
                    int bi = r >> 10, li = r & 1023;
                    __half* dst = (sec == 0) ? g_Q : (sec == 1) ? g_K : g_V;
                    *(__half2*)&dst[(((size_t)(bi * Hh + hh)) * Ls + li) * Dd + dd] =
                        __floats2half2_rn(v0, v1);
                }
            }
        }
    }
}

// ---------------------------------------------------------------------------
// Pass 1: per-key-column softmax stats.  GEMM1 B-frags now via ldmatrix.
// ---------------------------------------------------------------------------
__global__ void __launch_bounds__(256, 2) stats_kernel2() {
    __shared__ __half Ksm[128][72];
    __shared__ __half Qsm[128][72];

    const int jt = blockIdx.x, bh = blockIdx.y;
    const int t = threadIdx.x;
    const int lane = t & 31, wid = t >> 5;
    const int lr = lane >> 2, lc = lane & 3;
    const int wm = wid * 16;
    const int tr = t >> 3, tc = (t & 7) * 8;

    // B-frag ldsm geometry: 8-lane groups g: g0=(n,k) g1=(n,k+8) g2=(n+8,k) g3=(n+8,k+8)
    const int srow = (lane & 7) + ((lane >> 4) << 3);
    const int scol = ((lane >> 3) & 1) * 8;
    const unsigned qb_base = s2u(&Qsm[0][0]) + (srow * 72 + scol) * 2;

    const __half* Kp = g_K + ((size_t)bh * Ls + jt * 128) * Dd;
    const __half* Qp = g_Q + (size_t)bh * Ls * Dd;

#pragma unroll
    for (int i = 0; i < 4; i++) {
        int r = tr + 32 * i;
        *(uint4*)&Ksm[r][tc] = *(const uint4*)(Kp + (size_t)r * Dd + tc);
    }
    uint4 rq[4];
#pragma unroll
    for (int i = 0; i < 4; i++) {
        int r = tr + 32 * i;
        rq[i] = *(const uint4*)(Qp + (size_t)(jt * 128 + r) * Dd + tc);
    }
    __syncthreads();

    unsigned af[4][4];
#pragma unroll
    for (int ks = 0; ks < 4; ks++) {
        int k = ks * 16 + lc * 2;
        af[ks][0] = *(unsigned*)&Ksm[wm + lr][k];
        af[ks][1] = *(unsigned*)&Ksm[wm + lr + 8][k];
        af[ks][2] = *(unsigned*)&Ksm[wm + lr][k + 8];
        af[ks][3] = *(unsigned*)&Ksm[wm + lr + 8][k + 8];
    }

    float m0 = -3e38f, z0 = 0.f, m1 = -3e38f, z1 = 0.f;
    const int j0 = jt * 128 + wm + lr;
    const int j1 = j0 + 8;

    for (int it = jt; it < 8; it++) {
#pragma unroll
        for (int i = 0; i < 4; i++) {
            int r = tr + 32 * i;
            *(uint4*)&Qsm[r][tc] = rq[i];
        }
        __syncthreads();
        if (it + 1 < 8) {
#pragma unroll
            for (int i = 0; i < 4; i++) {
                int r = tr + 32 * i;
                rq[i] = *(const uint4*)(Qp + (size_t)((it + 1) * 128 + r) * Dd + tc);
            }
        }
        const bool diag = (it == jt);
#pragma unroll
        for (int ntp = 0; ntp < 8; ntp++) {
            float acc0[4] = {0.f, 0.f, 0.f, 0.f};
            float acc1[4] = {0.f, 0.f, 0.f, 0.f};
#pragma unroll
            for (int ks = 0; ks < 4; ks++) {
                unsigned bq[4];
                ldsm4(bq, qb_base + (ntp * 16 * 72 + ks * 16) * 2);
                mma16(acc0, af[ks], &bq[0]);
                mma16(acc1, af[ks], &bq[2]);
            }
            int i0 = it * 128 + ntp * 16 + lc * 2;
            int i1 = i0 + 8;
            if (!diag || i0 >= j0)     onl(m0, z0, acc0[0] * 0.125f);
            if (!diag || i0 + 1 >= j0) onl(m0, z0, acc0[1] * 0.125f);
            if (!diag || i0 >= j1)     onl(m1, z1, acc0[2] * 0.125f);
            if (!diag || i0 + 1 >= j1) onl(m1, z1, acc0[3] * 0.125f);
            if (!diag || i1 >= j0)     onl(m0, z0, acc1[0] * 0.125f);
            if (!diag || i1 + 1 >= j0) onl(m0, z0, acc1[1] * 0.125f);
            if (!diag || i1 >= j1)     onl(m1, z1, acc1[2] * 0.125f);
            if (!diag || i1 + 1 >= j1) onl(m1, z1, acc1[3] * 0.125f);
        }
        __syncthreads();
    }

#pragma unroll
    for (int off = 1; off <= 2; off <<= 1) {
        float mo = __shfl_xor_sync(0xFFFFFFFFu, m0, off);
        float zo = __shfl_xor_sync(0xFFFFFFFFu, z0, off);
        if (mo > m0) { z0 = z0 * __expf(m0 - mo) + zo; m0 = mo; }
        else         { z0 += zo * __expf(mo - m0); }
        mo = __shfl_xor_sync(0xFFFFFFFFu, m1, off);
        zo = __shfl_xor_sync(0xFFFFFFFFu, z1, off);
        if (mo > m1) { z1 = z1 * __expf(m1 - mo) + zo; m1 = mo; }
        else         { z1 += zo * __expf(mo - m1); }
    }
    if (lc == 0) {
        g_Mx[bh * Ls + j0] = m0;
        g_Zi[bh * Ls + j0] = 1.f / z0;
        g_Mx[bh * Ls + j1] = m1;
        g_Zi[bh * Ls + j1] = 1.f / z1;
    }
}

// ---------------------------------------------------------------------------
// Pass 2: fused attention.  GEMM1 B-frags + GEMM2 A-frags via ldmatrix.
// ---------------------------------------------------------------------------
constexpr int AT_KS = 128 * 136;
constexpr int AT_VS = AT_KS + 128 * 72;
constexpr int AT_HALFS = AT_VS + 128 * 72;
constexpr int P2_SMEM = AT_HALFS * 2 + 2 * 128 * 4;   // 72704 B

__global__ void __launch_bounds__(256, 2) attn_kernel2() {
    extern __shared__ __half smh[];
    __half* Ws  = smh;
    __half* Ksm = smh + AT_KS;
    __half* Vsm = smh + AT_VS;
    float* msm = (float*)(smh + AT_HALFS);
    float* zsm = msm + 128;

    const int it = 7 - blockIdx.x;
    const int bh = blockIdx.y;
    const int b = bh >> 4, h = bh & 15;
    const int t = threadIdx.x;
    const int lane = t & 31, wid = t >> 5;
    const int lr = lane >> 2, lc = lane & 3;
    const int wm = wid * 16;
    const int tr = t >> 3, tc = (t & 7) * 8;

    const __half* Qp = g_Q + ((size_t)bh * Ls + it * 128) * Dd;
    const __half* Kp = g_K + (size_t)bh * Ls * Dd;
    const __half* Vp = g_V + (size_t)bh * Ls * Dd;

    // V ldsm (trans) geometry
    const int vrow = (lane & 7) + ((lane >> 3) & 1) * 8;
    const int vcol = (lane >> 4) * 8;
    const unsigned Vbase = s2u(Vsm) + (vrow * 72 + vcol) * 2;
    // GEMM1 B-frag ldsm geometry on Ksm
    const int srow = (lane & 7) + ((lane >> 4) << 3);
    const int scol = ((lane >> 3) & 1) * 8;
    const unsigned kb_base = s2u(Ksm) + (srow * 72 + scol) * 2;
    // GEMM2 A-frag ldsm geometry on Ws (same qrow/qcol pattern as gemm_big)
    const unsigned ws_frag = s2u(Ws) + ((wm + vrow) * 136 + vcol) * 2;

#pragma unroll
    for (int i = 0; i < 4; i++) {
        int r = tr + 32 * i;
        *(uint4*)&Ksm[(size_t)r * 72 + tc] = *(const uint4*)(Qp + (size_t)r * Dd + tc);
    }
    __syncthreads();
    unsigned qf[4][4];
#pragma unroll
    for (int ks = 0; ks < 4; ks++) {
        int k = ks * 16 + lc * 2;
        qf[ks][0] = *(unsigned*)&Ksm[(wm + lr) * 72 + k];
        qf[ks][1] = *(unsigned*)&Ksm[(wm + lr + 8) * 72 + k];
        qf[ks][2] = *(unsigned*)&Ksm[(wm + lr) * 72 + k + 8];
        qf[ks][3] = *(unsigned*)&Ksm[(wm + lr + 8) * 72 + k + 8];
    }

    float yacc[8][4];
#pragma unroll
    for (int i = 0; i < 8; i++)
#pragma unroll
        for (int q = 0; q < 4; q++) yacc[i][q] = 0.f;

    uint4 rk[4], rv[4];
    float rstat;
#pragma unroll
    for (int i = 0; i < 4; i++) {
        int r = tr + 32 * i;
        rk[i] = *(const uint4*)(Kp + (size_t)r * Dd + tc);
        rv[i] = *(const uint4*)(Vp + (size_t)r * Dd + tc);
    }
    rstat = (t < 128) ? g_Mx[bh * Ls + t] : g_Zi[bh * Ls + (t - 128)];

    const int i0r = it * 128 + wm + lr;
    const int i1r = i0r + 8;

#pragma unroll 1
    for (int kt = 0; kt <= it; kt++) {
        __syncthreads();
#pragma unroll
        for (int i = 0; i < 4; i++) {
            int r = tr + 32 * i;
            *(uint4*)&Ksm[(size_t)r * 72 + tc] = rk[i];
            *(uint4*)&Vsm[(size_t)r * 72 + tc] = rv[i];
        }
        if (t < 128) msm[t] = rstat; else zsm[t - 128] = rstat;
        __syncthreads();

        if (kt < it) {
            int roff = (kt + 1) * 128;
#pragma unroll
            for (int i = 0; i < 4; i++) {
                int r = roff + tr + 32 * i;
                rk[i] = *(const uint4*)(Kp + (size_t)r * Dd + tc);
                rv[i] = *(const uint4*)(Vp + (size_t)r * Dd + tc);
            }
            rstat = (t < 128) ? g_Mx[bh * Ls + roff + t]
                              : g_Zi[bh * Ls + roff + (t - 128)];
        }

        const bool diag = (kt == it);
        // GEMM1: S tile + softmax weights -> Ws (warp-private rows)
#pragma unroll
        for (int ntp = 0; ntp < 8; ntp++) {
            float acc0[4] = {0.f, 0.f, 0.f, 0.f};
            float acc1[4] = {0.f, 0.f, 0.f, 0.f};
#pragma unroll
            for (int ks = 0; ks < 4; ks++) {
                unsigned bq[4];
                ldsm4(bq, kb_base + (ntp * 16 * 72 + ks * 16) * 2);
                mma16(acc0, qf[ks], &bq[0]);
                mma16(acc1, qf[ks], &bq[2]);
            }
            int jl0 = ntp * 16 + lc * 2;
            int jl1 = jl0 + 8;
            float w00 = __expf(acc0[0] * 0.125f - msm[jl0]) * zsm[jl0];
            float w01 = __expf(acc0[1] * 0.125f - msm[jl0 + 1]) * zsm[jl0 + 1];
            float w10 = __expf(acc0[2] * 0.125f - msm[jl0]) * zsm[jl0];
            float w11 = __expf(acc0[3] * 0.125f - msm[jl0 + 1]) * zsm[jl0 + 1];
            float w20 = __expf(acc1[0] * 0.125f - msm[jl1]) * zsm[jl1];
            float w21 = __expf(acc1[1] * 0.125f - msm[jl1 + 1]) * zsm[jl1 + 1];
            float w30 = __expf(acc1[2] * 0.125f - msm[jl1]) * zsm[jl1];
            float w31 = __expf(acc1[3] * 0.125f - msm[jl1 + 1]) * zsm[jl1 + 1];
            if (diag) {
                int jg0 = kt * 128 + jl0, jg1 = kt * 128 + jl1;
                if (i0r < jg0)     w00 = 0.f;
                if (i0r < jg0 + 1) w01 = 0.f;
                if (i1r < jg0)     w10 = 0.f;
                if (i1r < jg0 + 1) w11 = 0.f;
                if (i0r < jg1)     w20 = 0.f;
                if (i0r < jg1 + 1) w21 = 0.f;
                if (i1r < jg1)     w30 = 0.f;
                if (i1r < jg1 + 1) w31 = 0.f;
            }
            *(unsigned*)&Ws[(wm + lr) * 136 + jl0]     = pack2(w00, w01);
            *(unsigned*)&Ws[(wm + lr + 8) * 136 + jl0] = pack2(w10, w11);
            *(unsigned*)&Ws[(wm + lr) * 136 + jl1]     = pack2(w20, w21);
            *(unsigned*)&Ws[(wm + lr + 8) * 136 + jl1] = pack2(w30, w31);
        }
        __syncwarp();   // warp-private Ws rows

        // GEMM2: Y += Ws x V  (A-frags via ldsm4, V via ldsm4t)
#pragma unroll
        for (int ks = 0; ks < 8; ks++) {
            unsigned a2[4];
            ldsm4(a2, ws_frag + ks * 32);
#pragma unroll
            for (int dtp = 0; dtp < 4; dtp++) {
                unsigned bt[4];
                ldsm4t(bt, Vbase + ks * 16 * 144 + dtp * 32);
                mma16(yacc[dtp * 2],     a2, &bt[0]);
                mma16(yacc[dtp * 2 + 1], a2, &bt[2]);
            }
        }
    }

#pragma unroll
    for (int dt = 0; dt < 8; dt++) {
        int d0 = dt * 8 + lc * 2;
        *(__half2*)&g_Y[((size_t)(b * Ls + i0r)) * Cc + h * Dd + d0] =
            __floats2half2_rn(yacc[dt][0], yacc[dt][1]);
        *(__half2*)&g_Y[((size_t)(b * Ls + i1r)) * Cc + h * Dd + d0] =
            __floats2half2_rn(yacc[dt][2], yacc[dt][3]);
    }
}

// ---------------------------------------------------------------------------
// Launch
// ---------------------------------------------------------------------------
extern "C" void kernel_launch(void* const* d_in, const int* in_sizes, int n_in,
                              void* d_out, int out_size) {
    const float* x     = (const float*)d_in[0];
    const float* Wqkv  = (const float*)d_in[1];
    const float* bqkv  = (const float*)d_in[2];
    const float* Wproj = (const float*)d_in[3];
    const float* bproj = (const float*)d_in[4];
    float* out = (float*)d_out;

    __half *xh, *wq, *wp, *yh;
    cudaGetSymbolAddress((void**)&xh, g_Xh);
    cudaGetSymbolAddress((void**)&wq, g_Wqkvh);
    cudaGetSymbolAddress((void**)&wp, g_Wprojh);
    cudaGetSymbolAddress((void**)&yh, g_Y);

    (void)cudaFuncSetAttribute(gemm_big<NQKV, 1>,
                               cudaFuncAttributeMaxDynamicSharedMemorySize, GB_SMEM);
    (void)cudaFuncSetAttribute(gemm_big<Cc, 0>,
                               cudaFuncAttributeMaxDynamicSharedMemorySize, GB_SMEM);
    (void)cudaFuncSetAttribute(attn_kernel2,
                               cudaFuncAttributeMaxDynamicSharedMemorySize, P2_SMEM);

    // pre-passes: fp32 -> half
    conv_kernel<<<MT * Cc / 1024, 256>>>(x, xh);
    conv_kernel<<<Cc * NQKV / 1024, 256>>>(Wqkv, wq);
    conv_kernel<<<Cc * Cc / 1024, 256>>>(Wproj, wp);

    // QKV projection, scatter half into per-head Q/K/V
    gemm_big<NQKV, 1><<<dim3(MT / 128, NQKV / 256), 256, GB_SMEM>>>(xh, wq, bqkv, nullptr);
    // softmax stats + fused attention
    stats_kernel2<<<dim3(8, BHn), 256>>>();
    attn_kernel2<<<dim3(8, BHn), 256, P2_SMEM>>>();
    // output projection (fp32 out)
    gemm_big<Cc, 0><<<dim3(MT / 128, Cc / 256), 256, GB_SMEM>>>(yh, wp, bproj, out);
}